// round 11
// baseline (speedup 1.0000x reference)
#include <cuda_runtime.h>
#include <math.h>
#include <stdint.h>

// Shapes (fixed by the problem)
#define B_SZ   16
#define T_SEQ  1024
#define C_DIM  768
#define NH     12
#define DH     64
#define C3     2304       // 3*C
#define M_ROWS 16384      // B*T

// Scratch buffers (no cudaMalloc allowed)
__device__ float g_qkv[(size_t)M_ROWS * C3];   // [B*T, 3C]
__device__ float g_y[(size_t)M_ROWS * C_DIM];  // [B*T, C]

// ---------------------------------------------------------------------------
// Shared helpers
// ---------------------------------------------------------------------------
__device__ __forceinline__ uint32_t f2tf32(float x) {
    uint32_t y;
    asm volatile("cvt.rna.tf32.f32 %0, %1;" : "=r"(y) : "f"(x));
    return y;
}
__device__ __forceinline__ uint4 cvt4(float4 v) {
    return make_uint4(f2tf32(v.x), f2tf32(v.y), f2tf32(v.z), f2tf32(v.w));
}
__device__ __forceinline__ uint4 cvt4s(float4 v, float s) {
    return make_uint4(f2tf32(v.x * s), f2tf32(v.y * s), f2tf32(v.z * s), f2tf32(v.w * s));
}

__device__ __forceinline__ void mma_tf32(float* c, const uint32_t* a, const uint32_t* b) {
    asm volatile(
        "mma.sync.aligned.m16n8k8.row.col.f32.tf32.tf32.f32 "
        "{%0,%1,%2,%3}, {%4,%5,%6,%7}, {%8,%9}, {%0,%1,%2,%3};"
        : "+f"(c[0]), "+f"(c[1]), "+f"(c[2]), "+f"(c[3])
        : "r"(a[0]), "r"(a[1]), "r"(a[2]), "r"(a[3]), "r"(b[0]), "r"(b[1]));
}

// ---------------------------------------------------------------------------
// TF32 GEMM v5: C = A[M,K] @ B[K,N] + bias[N], row-major.
// CTA tile 128x128, 128 threads (4 warps, 2x2), warp tile 64x64, BK=32.
// Same warp-level reuse as v3 (128 B smem read / mma); smaller CTA so
// 2 CTAs co-reside per SM and cover each other's barrier/latency bubbles.
// R9 loop structure (LDG prefetch to regs, two syncs) — known good.
// ---------------------------------------------------------------------------
#define GBM 128
#define GBN 128
#define GBK 32
#define GAP 36    // As pitch (words)
#define GBP 136   // Bs pitch (words)
#define GEMM_SMEM ((GBM * GAP + GBK * GBP) * 4)   // 35840 B

__global__ __launch_bounds__(128, 2) void tf32_gemm_bias(
    const float* __restrict__ A, const float* __restrict__ B,
    const float* __restrict__ bias, float* __restrict__ C,
    int M, int N, int K)
{
    extern __shared__ uint32_t gsm[];
    uint32_t* As = gsm;                 // [GBM][GAP]
    uint32_t* Bs = gsm + GBM * GAP;     // [GBK][GBP]

    const int tid  = threadIdx.x;
    const int wid  = tid >> 5;
    const int lane = tid & 31;
    const int wm   = wid >> 1;      // 0..1  (64-row strip)
    const int wn   = wid & 1;       // 0..1  (64-col strip)
    const int g    = lane >> 2;     // 0..7
    const int tg   = lane & 3;      // 0..3

    // A loader: 8 passes, row = (tid>>3) + 16p, cols (tid&7)*4 .. +3
    const int arow = tid >> 3;          // 0..15
    const int acol = (tid & 7) * 4;     // 0..28
    // B loader: 8 passes, k = (tid>>5) + 4p, cols (tid&31)*4 .. +3
    const int bk   = tid >> 5;          // 0..3
    const int bcol = (tid & 31) * 4;    // 0..124

    const float* Ag = A + (size_t)(blockIdx.y * GBM + arow) * K + acol;
    const float* Bg = B + (size_t)bk * N + blockIdx.x * GBN + bcol;

    float acc[4][8][4];
#pragma unroll
    for (int mt = 0; mt < 4; mt++)
#pragma unroll
        for (int nt = 0; nt < 8; nt++)
#pragma unroll
            for (int c = 0; c < 4; c++) acc[mt][nt][c] = 0.f;

    float4 pa[8], pb[8];
#pragma unroll
    for (int p = 0; p < 8; p++) {
        pa[p] = *(const float4*)(Ag + (size_t)(16 * p) * K);
        pb[p] = *(const float4*)(Bg + (size_t)(4 * p) * N);
    }
#pragma unroll
    for (int p = 0; p < 8; p++) {
        *(uint4*)&As[(arow + 16 * p) * GAP + acol] = cvt4(pa[p]);
        *(uint4*)&Bs[(bk + 4 * p) * GBP + bcol]    = cvt4(pb[p]);
    }
    __syncthreads();

    for (int k0 = 0; k0 < K; k0 += GBK) {
        const bool has_next = (k0 + GBK) < K;
        if (has_next) {
#pragma unroll
            for (int p = 0; p < 8; p++) {
                pa[p] = *(const float4*)(Ag + (size_t)(16 * p) * K + k0 + GBK);
                pb[p] = *(const float4*)(Bg + (size_t)(k0 + GBK + 4 * p) * N);
            }
        }

#pragma unroll
        for (int ks = 0; ks < 4; ks++) {
            const int kk = ks * 8 + tg;
            uint32_t af[4][4], bf[8][2];
#pragma unroll
            for (int mt = 0; mt < 4; mt++) {
                const int am = wm * 64 + mt * 16;
                af[mt][0] = As[(am + g    ) * GAP + kk    ];
                af[mt][1] = As[(am + g + 8) * GAP + kk    ];
                af[mt][2] = As[(am + g    ) * GAP + kk + 4];
                af[mt][3] = As[(am + g + 8) * GAP + kk + 4];
            }
#pragma unroll
            for (int nt = 0; nt < 8; nt++) {
                const int bn = wn * 64 + nt * 8 + g;
                bf[nt][0] = Bs[(kk    ) * GBP + bn];
                bf[nt][1] = Bs[(kk + 4) * GBP + bn];
            }
#pragma unroll
            for (int mt = 0; mt < 4; mt++)
#pragma unroll
                for (int nt = 0; nt < 8; nt++)
                    mma_tf32(acc[mt][nt], af[mt], bf[nt]);
        }

        __syncthreads();
        if (has_next) {
#pragma unroll
            for (int p = 0; p < 8; p++) {
                *(uint4*)&As[(arow + 16 * p) * GAP + acol] = cvt4(pa[p]);
                *(uint4*)&Bs[(bk + 4 * p) * GBP + bcol]    = cvt4(pb[p]);
            }
            __syncthreads();
        }
    }

    const int crow0 = blockIdx.y * GBM + wm * 64;
    const int ccol0 = blockIdx.x * GBN + wn * 64;
#pragma unroll
    for (int mt = 0; mt < 4; mt++) {
#pragma unroll
        for (int nt = 0; nt < 8; nt++) {
            const int row = crow0 + mt * 16 + g;
            const int col = ccol0 + nt * 8 + 2 * tg;
            const float b0 = bias[col], b1 = bias[col + 1];
            float2 v0 = make_float2(acc[mt][nt][0] + b0, acc[mt][nt][1] + b1);
            float2 v1 = make_float2(acc[mt][nt][2] + b0, acc[mt][nt][3] + b1);
            *(float2*)(C + (size_t)row * N + col)       = v0;
            *(float2*)(C + (size_t)(row + 8) * N + col) = v1;
        }
    }
}

// ---------------------------------------------------------------------------
// Flash-attention v2 on mma.sync TF32 (R9 version — known good).
// q-tile 128, 4 warps; warp w owns rows 32w..32w+31 (mt=2 x 16-row).
// k-tile 64. Smem (uint32/float, pitch 68): Qs[128], Ks[64], Vs[64], Ps[128].
// ---------------------------------------------------------------------------
#define AP 68
#define ATTN_SMEM ((128 + 64 + 64 + 128) * AP * 4)   // 104448 B

__global__ __launch_bounds__(128) void attn_mma_kernel(
    const float* __restrict__ qkv, float* __restrict__ y)
{
    extern __shared__ uint32_t smu[];
    uint32_t* Qs = smu;                   // [128][AP]
    uint32_t* Ks = smu + 128 * AP;        // [64][AP]
    uint32_t* Vs = smu + 192 * AP;        // [64][AP]
    uint32_t* Ps = smu + 256 * AP;        // [128][AP]

    const int q0 = blockIdx.x * 128;
    const int h  = blockIdx.y;
    const int b  = blockIdx.z;

    const int tid  = threadIdx.x;
    const int w    = tid >> 5;
    const int lane = tid & 31;
    const int g    = lane >> 2;
    const int tg   = lane & 3;

    const int lr   = tid >> 1;            // 0..63
    const int colb = (tid & 1) * 16;      // 0 or 16

    // ---- load Q tile (128 rows, scaled, tf32) ----
#pragma unroll
    for (int rh = 0; rh < 2; rh++) {
        const int rr = lr + 64 * rh;
        const float* src = qkv + ((size_t)(b * T_SEQ + q0 + rr)) * C3 + h * DH;
        uint32_t* dst = Qs + rr * AP;
#pragma unroll
        for (int hs = 0; hs < 2; hs++) {
            const int c0 = colb + 32 * hs;
#pragma unroll
            for (int j = 0; j < 4; j++)
                *(uint4*)(dst + c0 + 4 * j) = cvt4s(*(const float4*)(src + c0 + 4 * j), 0.125f);
        }
    }

    float m[2][2], l[2][2], o[2][8][4];
#pragma unroll
    for (int mt = 0; mt < 2; mt++) {
        m[mt][0] = -1e30f; m[mt][1] = -1e30f;
        l[mt][0] = 0.f;    l[mt][1] = 0.f;
#pragma unroll
        for (int nt = 0; nt < 8; nt++)
#pragma unroll
            for (int c = 0; c < 4; c++) o[mt][nt][c] = 0.f;
    }

    const int rowg0 = 32 * w + g;
    const int kmax  = q0 + 64;

    for (int k0 = 0; k0 <= kmax; k0 += 64) {
        __syncthreads();
        // ---- load K and V tiles (64 rows, tf32) ----
        {
            const float* kb = qkv + ((size_t)(b * T_SEQ + k0 + lr)) * C3 + C_DIM + h * DH;
            const float* vb = qkv + ((size_t)(b * T_SEQ + k0 + lr)) * C3 + 2 * C_DIM + h * DH;
            uint32_t* kd = Ks + lr * AP;
            uint32_t* vd = Vs + lr * AP;
#pragma unroll
            for (int hs = 0; hs < 2; hs++) {
                const int c0 = colb + 32 * hs;
#pragma unroll
                for (int j = 0; j < 4; j++) {
                    *(uint4*)(kd + c0 + 4 * j) = cvt4(*(const float4*)(kb + c0 + 4 * j));
                    *(uint4*)(vd + c0 + 4 * j) = cvt4(*(const float4*)(vb + c0 + 4 * j));
                }
            }
        }
        __syncthreads();

        // ---- S = Q @ K^T : warp strip 32 x 64 ----
        float s[2][8][4];
#pragma unroll
        for (int mt = 0; mt < 2; mt++)
#pragma unroll
            for (int nt = 0; nt < 8; nt++)
#pragma unroll
                for (int c = 0; c < 4; c++) s[mt][nt][c] = 0.f;

#pragma unroll
        for (int ks = 0; ks < 8; ks++) {
            const int kk = ks * 8 + tg;
            uint32_t af[2][4];
#pragma unroll
            for (int mt = 0; mt < 2; mt++) {
                const int r = rowg0 + 16 * mt;
                af[mt][0] = Qs[(r    ) * AP + kk    ];
                af[mt][1] = Qs[(r + 8) * AP + kk    ];
                af[mt][2] = Qs[(r    ) * AP + kk + 4];
                af[mt][3] = Qs[(r + 8) * AP + kk + 4];
            }
#pragma unroll
            for (int nt = 0; nt < 8; nt++) {
                uint32_t bb[2];
                bb[0] = Ks[(nt * 8 + g) * AP + kk    ];
                bb[1] = Ks[(nt * 8 + g) * AP + kk + 4];
                mma_tf32(s[0][nt], af[0], bb);
                mma_tf32(s[1][nt], af[1], bb);
            }
        }

        // ---- causal mask (k0 >= q0 tiles) ----
        if (k0 >= q0) {
            const int dk = k0 - q0;
#pragma unroll
            for (int mt = 0; mt < 2; mt++) {
                const int r0 = rowg0 + 16 * mt;
#pragma unroll
                for (int nt = 0; nt < 8; nt++) {
                    const int c0 = nt * 8 + 2 * tg + dk;
                    if (c0     > r0    ) s[mt][nt][0] = -1e30f;
                    if (c0 + 1 > r0    ) s[mt][nt][1] = -1e30f;
                    if (c0     > r0 + 8) s[mt][nt][2] = -1e30f;
                    if (c0 + 1 > r0 + 8) s[mt][nt][3] = -1e30f;
                }
            }
        }

        // ---- online softmax (4 rows/thread, quad reductions) ----
#pragma unroll
        for (int mt = 0; mt < 2; mt++) {
            float mx0 = -1e30f, mx1 = -1e30f;
#pragma unroll
            for (int nt = 0; nt < 8; nt++) {
                mx0 = fmaxf(mx0, fmaxf(s[mt][nt][0], s[mt][nt][1]));
                mx1 = fmaxf(mx1, fmaxf(s[mt][nt][2], s[mt][nt][3]));
            }
            mx0 = fmaxf(mx0, __shfl_xor_sync(0xffffffffu, mx0, 1));
            mx0 = fmaxf(mx0, __shfl_xor_sync(0xffffffffu, mx0, 2));
            mx1 = fmaxf(mx1, __shfl_xor_sync(0xffffffffu, mx1, 1));
            mx1 = fmaxf(mx1, __shfl_xor_sync(0xffffffffu, mx1, 2));

            const float mn0 = fmaxf(m[mt][0], mx0);
            const float mn1 = fmaxf(m[mt][1], mx1);
            const float f0  = __expf(m[mt][0] - mn0);
            const float f1  = __expf(m[mt][1] - mn1);

            const int r0 = rowg0 + 16 * mt;
            float sum0 = 0.f, sum1 = 0.f;
#pragma unroll
            for (int nt = 0; nt < 8; nt++) {
                float p0 = __expf(s[mt][nt][0] - mn0);
                float p1 = __expf(s[mt][nt][1] - mn0);
                float p2 = __expf(s[mt][nt][2] - mn1);
                float p3 = __expf(s[mt][nt][3] - mn1);
                sum0 += p0 + p1;
                sum1 += p2 + p3;
                uint32_t* p0d = Ps + (r0    ) * AP + nt * 8 + 2 * tg;
                uint32_t* p1d = Ps + (r0 + 8) * AP + nt * 8 + 2 * tg;
                p0d[0] = f2tf32(p0); p0d[1] = f2tf32(p1);
                p1d[0] = f2tf32(p2); p1d[1] = f2tf32(p3);
            }
            sum0 += __shfl_xor_sync(0xffffffffu, sum0, 1);
            sum0 += __shfl_xor_sync(0xffffffffu, sum0, 2);
            sum1 += __shfl_xor_sync(0xffffffffu, sum1, 1);
            sum1 += __shfl_xor_sync(0xffffffffu, sum1, 2);

            l[mt][0] = l[mt][0] * f0 + sum0;  m[mt][0] = mn0;
            l[mt][1] = l[mt][1] * f1 + sum1;  m[mt][1] = mn1;
#pragma unroll
            for (int nt = 0; nt < 8; nt++) {
                o[mt][nt][0] *= f0; o[mt][nt][1] *= f0;
                o[mt][nt][2] *= f1; o[mt][nt][3] *= f1;
            }
        }
        __syncwarp();

        // ---- O += P @ V ----
#pragma unroll
        for (int ks = 0; ks < 8; ks++) {
            const int kk = ks * 8 + tg;
            uint32_t af[2][4];
#pragma unroll
            for (int mt = 0; mt < 2; mt++) {
                const int r = rowg0 + 16 * mt;
                af[mt][0] = Ps[(r    ) * AP + kk    ];
                af[mt][1] = Ps[(r + 8) * AP + kk    ];
                af[mt][2] = Ps[(r    ) * AP + kk + 4];
                af[mt][3] = Ps[(r + 8) * AP + kk + 4];
            }
#pragma unroll
            for (int nt = 0; nt < 8; nt++) {
                uint32_t bb[2];
                bb[0] = Vs[(kk    ) * AP + nt * 8 + g];
                bb[1] = Vs[(kk + 4) * AP + nt * 8 + g];
                mma_tf32(o[0][nt], af[0], bb);
                mma_tf32(o[1][nt], af[1], bb);
            }
        }
    }

    // ---- normalize, stage to smem, coalesced write ----
    __syncthreads();
    float* Of = (float*)Ps;
#pragma unroll
    for (int mt = 0; mt < 2; mt++) {
        const int r0 = rowg0 + 16 * mt;
        const float inv0 = 1.f / l[mt][0];
        const float inv1 = 1.f / l[mt][1];
#pragma unroll
        for (int nt = 0; nt < 8; nt++) {
            float* d0 = Of + (r0    ) * AP + nt * 8 + 2 * tg;
            float* d1 = Of + (r0 + 8) * AP + nt * 8 + 2 * tg;
            d0[0] = o[mt][nt][0] * inv0; d0[1] = o[mt][nt][1] * inv0;
            d1[0] = o[mt][nt][2] * inv1; d1[1] = o[mt][nt][3] * inv1;
        }
    }
    __syncthreads();
#pragma unroll
    for (int rh = 0; rh < 2; rh++) {
        const int rr = lr + 64 * rh;
        const float* src = Of + rr * AP;
        float* dst = y + ((size_t)(b * T_SEQ + q0 + rr)) * C_DIM + h * DH;
#pragma unroll
        for (int hs = 0; hs < 2; hs++) {
            const int c0 = colb + 32 * hs;
#pragma unroll
            for (int j = 0; j < 4; j++)
                *(float4*)(dst + c0 + 4 * j) = *(const float4*)(src + c0 + 4 * j);
        }
    }
}

// ---------------------------------------------------------------------------
extern "C" void kernel_launch(void* const* d_in, const int* in_sizes, int n_in,
                              void* d_out, int out_size)
{
    const float* x     = (const float*)d_in[0];
    const float* Wqkv  = (const float*)d_in[1];
    const float* bqkv  = (const float*)d_in[2];
    const float* Wproj = (const float*)d_in[3];
    const float* bproj = (const float*)d_in[4];
    float* out = (float*)d_out;

    float *qkv, *y;
    cudaGetSymbolAddress((void**)&qkv, g_qkv);
    cudaGetSymbolAddress((void**)&y, g_y);

    cudaFuncSetAttribute(tf32_gemm_bias,
                         cudaFuncAttributeMaxDynamicSharedMemorySize, GEMM_SMEM);
    cudaFuncSetAttribute(attn_mma_kernel,
                         cudaFuncAttributeMaxDynamicSharedMemorySize, ATTN_SMEM);

    // 1) QKV projection (tensor cores, TF32)
    tf32_gemm_bias<<<dim3(C3 / GBN, M_ROWS / GBM), 128, GEMM_SMEM>>>(
        x, Wqkv, bqkv, qkv, M_ROWS, C3, C_DIM);

    // 2) causal attention (tensor cores, TF32)
    attn_mma_kernel<<<dim3(T_SEQ / 128, NH, B_SZ), 128, ATTN_SMEM>>>(qkv, y);

    // 3) output projection (tensor cores, TF32)
    tf32_gemm_bias<<<dim3(C_DIM / GBN, M_ROWS / GBM), 128, GEMM_SMEM>>>(
        y, Wproj, bproj, out, M_ROWS, C_DIM, C_DIM);
}

// round 12
// speedup vs baseline: 1.2671x; 1.2671x over previous
#include <cuda_runtime.h>
#include <cuda_fp16.h>
#include <math.h>
#include <stdint.h>

// Shapes (fixed by the problem)
#define B_SZ   16
#define T_SEQ  1024
#define C_DIM  768
#define NH     12
#define DH     64
#define C3     2304       // 3*C
#define M_ROWS 16384      // B*T

// Scratch buffers (no cudaMalloc allowed)
__device__ float g_qkv[(size_t)M_ROWS * C3];   // [B*T, 3C]
__device__ float g_y[(size_t)M_ROWS * C_DIM];  // [B*T, C]

// ---------------------------------------------------------------------------
// Shared helpers
// ---------------------------------------------------------------------------
__device__ __forceinline__ uint32_t f2tf32(float x) {
    uint32_t y;
    asm volatile("cvt.rna.tf32.f32 %0, %1;" : "=r"(y) : "f"(x));
    return y;
}
__device__ __forceinline__ uint4 cvt4(float4 v) {
    return make_uint4(f2tf32(v.x), f2tf32(v.y), f2tf32(v.z), f2tf32(v.w));
}
__device__ __forceinline__ uint4 cvt4s(float4 v, float s) {
    return make_uint4(f2tf32(v.x * s), f2tf32(v.y * s), f2tf32(v.z * s), f2tf32(v.w * s));
}
__device__ __forceinline__ uint32_t packh2(float a, float b) {
    __half2 h = __floats2half2_rn(a, b);
    return *(uint32_t*)&h;
}

__device__ __forceinline__ void mma_tf32(float* c, const uint32_t* a, const uint32_t* b) {
    asm volatile(
        "mma.sync.aligned.m16n8k8.row.col.f32.tf32.tf32.f32 "
        "{%0,%1,%2,%3}, {%4,%5,%6,%7}, {%8,%9}, {%0,%1,%2,%3};"
        : "+f"(c[0]), "+f"(c[1]), "+f"(c[2]), "+f"(c[3])
        : "r"(a[0]), "r"(a[1]), "r"(a[2]), "r"(a[3]), "r"(b[0]), "r"(b[1]));
}
__device__ __forceinline__ void mma_f16(float* c, const uint32_t* a, const uint32_t* b) {
    asm volatile(
        "mma.sync.aligned.m16n8k16.row.col.f32.f16.f16.f32 "
        "{%0,%1,%2,%3}, {%4,%5,%6,%7}, {%8,%9}, {%0,%1,%2,%3};"
        : "+f"(c[0]), "+f"(c[1]), "+f"(c[2]), "+f"(c[3])
        : "r"(a[0]), "r"(a[1]), "r"(a[2]), "r"(a[3]), "r"(b[0]), "r"(b[1]));
}

// ---------------------------------------------------------------------------
// FP16 GEMM v6: C = A[M,K] @ B[K,N] + bias[N], row-major, fp32 accum.
// CTA 256x128, 8 warps (4x2), warp tile 64x64, BK=32 (2 k16 mma steps).
// A smem [256 rows][16 half-pairs], B smem [128 n][16 half-pairs] (k-major).
// Pitch 20 words: fragment LDS banks (20g+tg) mod 32 — fully conflict-free.
// R9 loop structure (reg prefetch, 2 syncs per chunk) — known good.
// ---------------------------------------------------------------------------
#define GBM 256
#define GBN 128
#define GBK 32
#define AP16 20   // word pitch (16 pairs + 4 pad)
#define BP16 20

__global__ __launch_bounds__(256, 1) void f16_gemm_bias(
    const float* __restrict__ A, const float* __restrict__ B,
    const float* __restrict__ bias, float* __restrict__ C,
    int M, int N, int K)
{
    __shared__ uint32_t Asf[GBM * AP16];   // 20480 B
    __shared__ uint32_t Bsf[GBN * BP16];   // 10240 B

    const int tid  = threadIdx.x;
    const int wid  = tid >> 5;
    const int lane = tid & 31;
    const int wm   = wid >> 1;      // 0..3  (64-row strip)
    const int wn   = wid & 1;       // 0..1  (64-col strip)
    const int g    = lane >> 2;     // 0..7
    const int tg   = lane & 3;      // 0..3

    // A loader: rows ar+32i (i=0..7), 4 floats at col ac (coalesced 128B/8thr)
    const int ar = tid >> 3;            // 0..31
    const int ac = (tid & 7) * 4;       // 0..28
    // B loader: n-row bn_l, 8 k-pairs starting at bkh (k-major smem)
    const int bn_l = tid & 127;         // 0..127
    const int bkh  = (tid >> 7) * 8;    // 0 or 8

    const float* Ag = A + (size_t)(blockIdx.y * GBM + ar) * K + ac;
    const float* Bg = B + (size_t)(2 * bkh) * N + blockIdx.x * GBN + bn_l;

    float acc[4][8][4];
#pragma unroll
    for (int mt = 0; mt < 4; mt++)
#pragma unroll
        for (int nt = 0; nt < 8; nt++)
#pragma unroll
            for (int c = 0; c < 4; c++) acc[mt][nt][c] = 0.f;

    float4 pa[8];
    float  pbl[8], pbh[8];

    // ---- prologue: load chunk 0, convert+store, sync ----
#pragma unroll
    for (int i = 0; i < 8; i++) pa[i] = *(const float4*)(Ag + (size_t)(32 * i) * K);
#pragma unroll
    for (int i = 0; i < 8; i++) {
        pbl[i] = Bg[(size_t)(2 * i) * N];
        pbh[i] = Bg[(size_t)(2 * i + 1) * N];
    }
#pragma unroll
    for (int i = 0; i < 8; i++) {
        uint2 v = make_uint2(packh2(pa[i].x, pa[i].y), packh2(pa[i].z, pa[i].w));
        *(uint2*)&Asf[(ar + 32 * i) * AP16 + (ac >> 1)] = v;
        Bsf[bn_l * BP16 + bkh + i] = packh2(pbl[i], pbh[i]);
    }
    __syncthreads();

    for (int k0 = 0; k0 < K; k0 += GBK) {
        const bool has_next = (k0 + GBK) < K;
        if (has_next) {
#pragma unroll
            for (int i = 0; i < 8; i++)
                pa[i] = *(const float4*)(Ag + (size_t)(32 * i) * K + k0 + GBK);
#pragma unroll
            for (int i = 0; i < 8; i++) {
                pbl[i] = Bg[(size_t)(k0 + GBK + 2 * i) * N];
                pbh[i] = Bg[(size_t)(k0 + GBK + 2 * i + 1) * N];
            }
        }

        // compute: 2 k16 steps
#pragma unroll
        for (int ks = 0; ks < 2; ks++) {
            const int kp = ks * 8 + tg;
            uint32_t af[4][4], bf[8][2];
#pragma unroll
            for (int mt = 0; mt < 4; mt++) {
                const int am = wm * 64 + mt * 16;
                af[mt][0] = Asf[(am + g    ) * AP16 + kp    ];
                af[mt][1] = Asf[(am + g + 8) * AP16 + kp    ];
                af[mt][2] = Asf[(am + g    ) * AP16 + kp + 4];
                af[mt][3] = Asf[(am + g + 8) * AP16 + kp + 4];
            }
#pragma unroll
            for (int nt = 0; nt < 8; nt++) {
                const int bn = wn * 64 + nt * 8 + g;
                bf[nt][0] = Bsf[bn * BP16 + kp    ];
                bf[nt][1] = Bsf[bn * BP16 + kp + 4];
            }
#pragma unroll
            for (int mt = 0; mt < 4; mt++)
#pragma unroll
                for (int nt = 0; nt < 8; nt++)
                    mma_f16(acc[mt][nt], af[mt], bf[nt]);
        }

        __syncthreads();
        if (has_next) {
#pragma unroll
            for (int i = 0; i < 8; i++) {
                uint2 v = make_uint2(packh2(pa[i].x, pa[i].y), packh2(pa[i].z, pa[i].w));
                *(uint2*)&Asf[(ar + 32 * i) * AP16 + (ac >> 1)] = v;
                Bsf[bn_l * BP16 + bkh + i] = packh2(pbl[i], pbh[i]);
            }
            __syncthreads();
        }
    }

    const int crow0 = blockIdx.y * GBM + wm * 64;
    const int ccol0 = blockIdx.x * GBN + wn * 64;
#pragma unroll
    for (int mt = 0; mt < 4; mt++) {
#pragma unroll
        for (int nt = 0; nt < 8; nt++) {
            const int row = crow0 + mt * 16 + g;
            const int col = ccol0 + nt * 8 + 2 * tg;
            const float b0 = bias[col], b1 = bias[col + 1];
            float2 v0 = make_float2(acc[mt][nt][0] + b0, acc[mt][nt][1] + b1);
            float2 v1 = make_float2(acc[mt][nt][2] + b0, acc[mt][nt][3] + b1);
            *(float2*)(C + (size_t)row * N + col)       = v0;
            *(float2*)(C + (size_t)(row + 8) * N + col) = v1;
        }
    }
}

// ---------------------------------------------------------------------------
// Flash-attention v2 on mma.sync TF32 (R9 version — known good, unchanged).
// q-tile 128, 4 warps; warp w owns rows 32w..32w+31 (mt=2 x 16-row).
// ---------------------------------------------------------------------------
#define AP 68
#define ATTN_SMEM ((128 + 64 + 64 + 128) * AP * 4)   // 104448 B

__global__ __launch_bounds__(128) void attn_mma_kernel(
    const float* __restrict__ qkv, float* __restrict__ y)
{
    extern __shared__ uint32_t smu[];
    uint32_t* Qs = smu;                   // [128][AP]
    uint32_t* Ks = smu + 128 * AP;        // [64][AP]
    uint32_t* Vs = smu + 192 * AP;        // [64][AP]
    uint32_t* Ps = smu + 256 * AP;        // [128][AP]

    const int q0 = blockIdx.x * 128;
    const int h  = blockIdx.y;
    const int b  = blockIdx.z;

    const int tid  = threadIdx.x;
    const int w    = tid >> 5;
    const int lane = tid & 31;
    const int g    = lane >> 2;
    const int tg   = lane & 3;

    const int lr   = tid >> 1;            // 0..63
    const int colb = (tid & 1) * 16;      // 0 or 16

#pragma unroll
    for (int rh = 0; rh < 2; rh++) {
        const int rr = lr + 64 * rh;
        const float* src = qkv + ((size_t)(b * T_SEQ + q0 + rr)) * C3 + h * DH;
        uint32_t* dst = Qs + rr * AP;
#pragma unroll
        for (int hs = 0; hs < 2; hs++) {
            const int c0 = colb + 32 * hs;
#pragma unroll
            for (int j = 0; j < 4; j++)
                *(uint4*)(dst + c0 + 4 * j) = cvt4s(*(const float4*)(src + c0 + 4 * j), 0.125f);
        }
    }

    float m[2][2], l[2][2], o[2][8][4];
#pragma unroll
    for (int mt = 0; mt < 2; mt++) {
        m[mt][0] = -1e30f; m[mt][1] = -1e30f;
        l[mt][0] = 0.f;    l[mt][1] = 0.f;
#pragma unroll
        for (int nt = 0; nt < 8; nt++)
#pragma unroll
            for (int c = 0; c < 4; c++) o[mt][nt][c] = 0.f;
    }

    const int rowg0 = 32 * w + g;
    const int kmax  = q0 + 64;

    for (int k0 = 0; k0 <= kmax; k0 += 64) {
        __syncthreads();
        {
            const float* kb = qkv + ((size_t)(b * T_SEQ + k0 + lr)) * C3 + C_DIM + h * DH;
            const float* vb = qkv + ((size_t)(b * T_SEQ + k0 + lr)) * C3 + 2 * C_DIM + h * DH;
            uint32_t* kd = Ks + lr * AP;
            uint32_t* vd = Vs + lr * AP;
#pragma unroll
            for (int hs = 0; hs < 2; hs++) {
                const int c0 = colb + 32 * hs;
#pragma unroll
                for (int j = 0; j < 4; j++) {
                    *(uint4*)(kd + c0 + 4 * j) = cvt4(*(const float4*)(kb + c0 + 4 * j));
                    *(uint4*)(vd + c0 + 4 * j) = cvt4(*(const float4*)(vb + c0 + 4 * j));
                }
            }
        }
        __syncthreads();

        float s[2][8][4];
#pragma unroll
        for (int mt = 0; mt < 2; mt++)
#pragma unroll
            for (int nt = 0; nt < 8; nt++)
#pragma unroll
                for (int c = 0; c < 4; c++) s[mt][nt][c] = 0.f;

#pragma unroll
        for (int ks = 0; ks < 8; ks++) {
            const int kk = ks * 8 + tg;
            uint32_t af[2][4];
#pragma unroll
            for (int mt = 0; mt < 2; mt++) {
                const int r = rowg0 + 16 * mt;
                af[mt][0] = Qs[(r    ) * AP + kk    ];
                af[mt][1] = Qs[(r + 8) * AP + kk    ];
                af[mt][2] = Qs[(r    ) * AP + kk + 4];
                af[mt][3] = Qs[(r + 8) * AP + kk + 4];
            }
#pragma unroll
            for (int nt = 0; nt < 8; nt++) {
                uint32_t bb[2];
                bb[0] = Ks[(nt * 8 + g) * AP + kk    ];
                bb[1] = Ks[(nt * 8 + g) * AP + kk + 4];
                mma_tf32(s[0][nt], af[0], bb);
                mma_tf32(s[1][nt], af[1], bb);
            }
        }

        if (k0 >= q0) {
            const int dk = k0 - q0;
#pragma unroll
            for (int mt = 0; mt < 2; mt++) {
                const int r0 = rowg0 + 16 * mt;
#pragma unroll
                for (int nt = 0; nt < 8; nt++) {
                    const int c0 = nt * 8 + 2 * tg + dk;
                    if (c0     > r0    ) s[mt][nt][0] = -1e30f;
                    if (c0 + 1 > r0    ) s[mt][nt][1] = -1e30f;
                    if (c0     > r0 + 8) s[mt][nt][2] = -1e30f;
                    if (c0 + 1 > r0 + 8) s[mt][nt][3] = -1e30f;
                }
            }
        }

#pragma unroll
        for (int mt = 0; mt < 2; mt++) {
            float mx0 = -1e30f, mx1 = -1e30f;
#pragma unroll
            for (int nt = 0; nt < 8; nt++) {
                mx0 = fmaxf(mx0, fmaxf(s[mt][nt][0], s[mt][nt][1]));
                mx1 = fmaxf(mx1, fmaxf(s[mt][nt][2], s[mt][nt][3]));
            }
            mx0 = fmaxf(mx0, __shfl_xor_sync(0xffffffffu, mx0, 1));
            mx0 = fmaxf(mx0, __shfl_xor_sync(0xffffffffu, mx0, 2));
            mx1 = fmaxf(mx1, __shfl_xor_sync(0xffffffffu, mx1, 1));
            mx1 = fmaxf(mx1, __shfl_xor_sync(0xffffffffu, mx1, 2));

            const float mn0 = fmaxf(m[mt][0], mx0);
            const float mn1 = fmaxf(m[mt][1], mx1);
            const float f0  = __expf(m[mt][0] - mn0);
            const float f1  = __expf(m[mt][1] - mn1);

            const int r0 = rowg0 + 16 * mt;
            float sum0 = 0.f, sum1 = 0.f;
#pragma unroll
            for (int nt = 0; nt < 8; nt++) {
                float p0 = __expf(s[mt][nt][0] - mn0);
                float p1 = __expf(s[mt][nt][1] - mn0);
                float p2 = __expf(s[mt][nt][2] - mn1);
                float p3 = __expf(s[mt][nt][3] - mn1);
                sum0 += p0 + p1;
                sum1 += p2 + p3;
                uint32_t* p0d = Ps + (r0    ) * AP + nt * 8 + 2 * tg;
                uint32_t* p1d = Ps + (r0 + 8) * AP + nt * 8 + 2 * tg;
                p0d[0] = f2tf32(p0); p0d[1] = f2tf32(p1);
                p1d[0] = f2tf32(p2); p1d[1] = f2tf32(p3);
            }
            sum0 += __shfl_xor_sync(0xffffffffu, sum0, 1);
            sum0 += __shfl_xor_sync(0xffffffffu, sum0, 2);
            sum1 += __shfl_xor_sync(0xffffffffu, sum1, 1);
            sum1 += __shfl_xor_sync(0xffffffffu, sum1, 2);

            l[mt][0] = l[mt][0] * f0 + sum0;  m[mt][0] = mn0;
            l[mt][1] = l[mt][1] * f1 + sum1;  m[mt][1] = mn1;
#pragma unroll
            for (int nt = 0; nt < 8; nt++) {
                o[mt][nt][0] *= f0; o[mt][nt][1] *= f0;
                o[mt][nt][2] *= f1; o[mt][nt][3] *= f1;
            }
        }
        __syncwarp();

#pragma unroll
        for (int ks = 0; ks < 8; ks++) {
            const int kk = ks * 8 + tg;
            uint32_t af[2][4];
#pragma unroll
            for (int mt = 0; mt < 2; mt++) {
                const int r = rowg0 + 16 * mt;
                af[mt][0] = Ps[(r    ) * AP + kk    ];
                af[mt][1] = Ps[(r + 8) * AP + kk    ];
                af[mt][2] = Ps[(r    ) * AP + kk + 4];
                af[mt][3] = Ps[(r + 8) * AP + kk + 4];
            }
#pragma unroll
            for (int nt = 0; nt < 8; nt++) {
                uint32_t bb[2];
                bb[0] = Vs[(kk    ) * AP + nt * 8 + g];
                bb[1] = Vs[(kk + 4) * AP + nt * 8 + g];
                mma_tf32(o[0][nt], af[0], bb);
                mma_tf32(o[1][nt], af[1], bb);
            }
        }
    }

    __syncthreads();
    float* Of = (float*)Ps;
#pragma unroll
    for (int mt = 0; mt < 2; mt++) {
        const int r0 = rowg0 + 16 * mt;
        const float inv0 = 1.f / l[mt][0];
        const float inv1 = 1.f / l[mt][1];
#pragma unroll
        for (int nt = 0; nt < 8; nt++) {
            float* d0 = Of + (r0    ) * AP + nt * 8 + 2 * tg;
            float* d1 = Of + (r0 + 8) * AP + nt * 8 + 2 * tg;
            d0[0] = o[mt][nt][0] * inv0; d0[1] = o[mt][nt][1] * inv0;
            d1[0] = o[mt][nt][2] * inv1; d1[1] = o[mt][nt][3] * inv1;
        }
    }
    __syncthreads();
#pragma unroll
    for (int rh = 0; rh < 2; rh++) {
        const int rr = lr + 64 * rh;
        const float* src = Of + rr * AP;
        float* dst = y + ((size_t)(b * T_SEQ + q0 + rr)) * C_DIM + h * DH;
#pragma unroll
        for (int hs = 0; hs < 2; hs++) {
            const int c0 = colb + 32 * hs;
#pragma unroll
            for (int j = 0; j < 4; j++)
                *(float4*)(dst + c0 + 4 * j) = *(const float4*)(src + c0 + 4 * j);
        }
    }
}

// ---------------------------------------------------------------------------
extern "C" void kernel_launch(void* const* d_in, const int* in_sizes, int n_in,
                              void* d_out, int out_size)
{
    const float* x     = (const float*)d_in[0];
    const float* Wqkv  = (const float*)d_in[1];
    const float* bqkv  = (const float*)d_in[2];
    const float* Wproj = (const float*)d_in[3];
    const float* bproj = (const float*)d_in[4];
    float* out = (float*)d_out;

    float *qkv, *y;
    cudaGetSymbolAddress((void**)&qkv, g_qkv);
    cudaGetSymbolAddress((void**)&y, g_y);

    cudaFuncSetAttribute(attn_mma_kernel,
                         cudaFuncAttributeMaxDynamicSharedMemorySize, ATTN_SMEM);

    // 1) QKV projection (tensor cores, FP16 x FP16 -> FP32)
    f16_gemm_bias<<<dim3(C3 / GBN, M_ROWS / GBM), 256>>>(
        x, Wqkv, bqkv, qkv, M_ROWS, C3, C_DIM);

    // 2) causal attention (tensor cores, TF32)
    attn_mma_kernel<<<dim3(T_SEQ / 128, NH, B_SZ), 128, ATTN_SMEM>>>(qkv, y);

    // 3) output projection (tensor cores, FP16 x FP16 -> FP32)
    f16_gemm_bias<<<dim3(C_DIM / GBN, M_ROWS / GBM), 256>>>(
        y, Wproj, bproj, out, M_ROWS, C_DIM, C_DIM);
}

// round 13
// speedup vs baseline: 1.4918x; 1.1774x over previous
#include <cuda_runtime.h>
#include <cuda_fp16.h>
#include <math.h>
#include <stdint.h>

// Shapes (fixed by the problem)
#define B_SZ   16
#define T_SEQ  1024
#define C_DIM  768
#define NH     12
#define DH     64
#define C3     2304       // 3*C
#define M_ROWS 16384      // B*T

// Scratch buffers (no cudaMalloc allowed)
__device__ float g_qkv[(size_t)M_ROWS * C3];   // [B*T, 3C]
__device__ float g_y[(size_t)M_ROWS * C_DIM];  // [B*T, C]

// ---------------------------------------------------------------------------
// Shared helpers
// ---------------------------------------------------------------------------
__device__ __forceinline__ uint32_t packh2(float a, float b) {
    __half2 h = __floats2half2_rn(a, b);
    return *(uint32_t*)&h;
}

__device__ __forceinline__ void mma_f16(float* c, const uint32_t* a, const uint32_t* b) {
    asm volatile(
        "mma.sync.aligned.m16n8k16.row.col.f32.f16.f16.f32 "
        "{%0,%1,%2,%3}, {%4,%5,%6,%7}, {%8,%9}, {%0,%1,%2,%3};"
        : "+f"(c[0]), "+f"(c[1]), "+f"(c[2]), "+f"(c[3])
        : "r"(a[0]), "r"(a[1]), "r"(a[2]), "r"(a[3]), "r"(b[0]), "r"(b[1]));
}

// ---------------------------------------------------------------------------
// FP16 GEMM v6 (unchanged from R12 — known good).
// CTA 256x128, 8 warps (4x2), warp tile 64x64, BK=32 (2 k16 mma steps).
// ---------------------------------------------------------------------------
#define GBM 256
#define GBN 128
#define GBK 32
#define AP16 20
#define BP16 20

__global__ __launch_bounds__(256, 1) void f16_gemm_bias(
    const float* __restrict__ A, const float* __restrict__ B,
    const float* __restrict__ bias, float* __restrict__ C,
    int M, int N, int K)
{
    __shared__ uint32_t Asf[GBM * AP16];
    __shared__ uint32_t Bsf[GBN * BP16];

    const int tid  = threadIdx.x;
    const int wid  = tid >> 5;
    const int lane = tid & 31;
    const int wm   = wid >> 1;
    const int wn   = wid & 1;
    const int g    = lane >> 2;
    const int tg   = lane & 3;

    const int ar = tid >> 3;
    const int ac = (tid & 7) * 4;
    const int bn_l = tid & 127;
    const int bkh  = (tid >> 7) * 8;

    const float* Ag = A + (size_t)(blockIdx.y * GBM + ar) * K + ac;
    const float* Bg = B + (size_t)(2 * bkh) * N + blockIdx.x * GBN + bn_l;

    float acc[4][8][4];
#pragma unroll
    for (int mt = 0; mt < 4; mt++)
#pragma unroll
        for (int nt = 0; nt < 8; nt++)
#pragma unroll
            for (int c = 0; c < 4; c++) acc[mt][nt][c] = 0.f;

    float4 pa[8];
    float  pbl[8], pbh[8];

#pragma unroll
    for (int i = 0; i < 8; i++) pa[i] = *(const float4*)(Ag + (size_t)(32 * i) * K);
#pragma unroll
    for (int i = 0; i < 8; i++) {
        pbl[i] = Bg[(size_t)(2 * i) * N];
        pbh[i] = Bg[(size_t)(2 * i + 1) * N];
    }
#pragma unroll
    for (int i = 0; i < 8; i++) {
        uint2 v = make_uint2(packh2(pa[i].x, pa[i].y), packh2(pa[i].z, pa[i].w));
        *(uint2*)&Asf[(ar + 32 * i) * AP16 + (ac >> 1)] = v;
        Bsf[bn_l * BP16 + bkh + i] = packh2(pbl[i], pbh[i]);
    }
    __syncthreads();

    for (int k0 = 0; k0 < K; k0 += GBK) {
        const bool has_next = (k0 + GBK) < K;
        if (has_next) {
#pragma unroll
            for (int i = 0; i < 8; i++)
                pa[i] = *(const float4*)(Ag + (size_t)(32 * i) * K + k0 + GBK);
#pragma unroll
            for (int i = 0; i < 8; i++) {
                pbl[i] = Bg[(size_t)(k0 + GBK + 2 * i) * N];
                pbh[i] = Bg[(size_t)(k0 + GBK + 2 * i + 1) * N];
            }
        }

#pragma unroll
        for (int ks = 0; ks < 2; ks++) {
            const int kp = ks * 8 + tg;
            uint32_t af[4][4], bf[8][2];
#pragma unroll
            for (int mt = 0; mt < 4; mt++) {
                const int am = wm * 64 + mt * 16;
                af[mt][0] = Asf[(am + g    ) * AP16 + kp    ];
                af[mt][1] = Asf[(am + g + 8) * AP16 + kp    ];
                af[mt][2] = Asf[(am + g    ) * AP16 + kp + 4];
                af[mt][3] = Asf[(am + g + 8) * AP16 + kp + 4];
            }
#pragma unroll
            for (int nt = 0; nt < 8; nt++) {
                const int bn = wn * 64 + nt * 8 + g;
                bf[nt][0] = Bsf[bn * BP16 + kp    ];
                bf[nt][1] = Bsf[bn * BP16 + kp + 4];
            }
#pragma unroll
            for (int mt = 0; mt < 4; mt++)
#pragma unroll
                for (int nt = 0; nt < 8; nt++)
                    mma_f16(acc[mt][nt], af[mt], bf[nt]);
        }

        __syncthreads();
        if (has_next) {
#pragma unroll
            for (int i = 0; i < 8; i++) {
                uint2 v = make_uint2(packh2(pa[i].x, pa[i].y), packh2(pa[i].z, pa[i].w));
                *(uint2*)&Asf[(ar + 32 * i) * AP16 + (ac >> 1)] = v;
                Bsf[bn_l * BP16 + bkh + i] = packh2(pbl[i], pbh[i]);
            }
            __syncthreads();
        }
    }

    const int crow0 = blockIdx.y * GBM + wm * 64;
    const int ccol0 = blockIdx.x * GBN + wn * 64;
#pragma unroll
    for (int mt = 0; mt < 4; mt++) {
#pragma unroll
        for (int nt = 0; nt < 8; nt++) {
            const int row = crow0 + mt * 16 + g;
            const int col = ccol0 + nt * 8 + 2 * tg;
            const float b0 = bias[col], b1 = bias[col + 1];
            float2 v0 = make_float2(acc[mt][nt][0] + b0, acc[mt][nt][1] + b1);
            float2 v1 = make_float2(acc[mt][nt][2] + b0, acc[mt][nt][3] + b1);
            *(float2*)(C + (size_t)row * N + col)       = v0;
            *(float2*)(C + (size_t)(row + 8) * N + col) = v1;
        }
    }
}

// ---------------------------------------------------------------------------
// Flash-attention v4 on mma.sync FP16 (m16n8k16, fp32 accum).
// q-tile 128, 4 warps; warp w owns rows 32w..32w+31 (mt=2 x 16-row).
// Half-pair smem, pitch HP=36 words:
//   Qh[128][HP] (q row, d-pairs)     Kh[64][HP] (key row, d-pairs)
//   Vt[64][HP]  (d row, key-pairs)   Ph[128][HP] (q row, key-pairs)
// All fragment LDS banks are (4g + tg + const) mod 32 — conflict-free.
// O staged as float (pitch 68) over the Qh/Kh/Vt region at the end.
// ---------------------------------------------------------------------------
#define HP 36
#define ATTN_SMEM ((128 + 64 + 64 + 128) * HP * 4)   // 55296 B

__global__ __launch_bounds__(128, 2) void attn_mma_kernel(
    const float* __restrict__ qkv, float* __restrict__ y)
{
    extern __shared__ uint32_t smu[];
    uint32_t* Qh = smu;                   // [128][HP]
    uint32_t* Kh = smu + 128 * HP;        // [64][HP]
    uint32_t* Vt = smu + 192 * HP;        // [64][HP]
    uint32_t* Ph = smu + 256 * HP;        // [128][HP]

    const int q0 = blockIdx.x * 128;
    const int h  = blockIdx.y;
    const int b  = blockIdx.z;

    const int tid  = threadIdx.x;
    const int w    = tid >> 5;
    const int lane = tid & 31;
    const int g    = lane >> 2;
    const int tg   = lane & 3;

    // Q/K loader: 2 threads per row, 16-float segments at colb and colb+32
    const int lr   = tid >> 1;            // 0..63
    const int colb = (tid & 1) * 16;      // 0 or 16
    // V loader: token pair r (2r, 2r+1), 16-d segment
    const int vr   = tid & 31;            // token pair 0..31
    const int vds  = (tid >> 5) * 16;     // d base 0/16/32/48

    // ---- load Q tile (128 rows, scaled, packed half pairs) ----
#pragma unroll
    for (int rh = 0; rh < 2; rh++) {
        const int rr = lr + 64 * rh;
        const float* src = qkv + ((size_t)(b * T_SEQ + q0 + rr)) * C3 + h * DH;
        uint32_t* dst = Qh + rr * HP;
#pragma unroll
        for (int hs = 0; hs < 2; hs++) {
            const int c0 = colb + 32 * hs;       // float col base
            const int p0 = (colb >> 1) + 16 * hs; // pair base
#pragma unroll
            for (int j = 0; j < 2; j++) {
                float4 a = *(const float4*)(src + c0 + 8 * j);
                float4 bq = *(const float4*)(src + c0 + 8 * j + 4);
                uint4 v;
                v.x = packh2(a.x * 0.125f, a.y * 0.125f);
                v.y = packh2(a.z * 0.125f, a.w * 0.125f);
                v.z = packh2(bq.x * 0.125f, bq.y * 0.125f);
                v.w = packh2(bq.z * 0.125f, bq.w * 0.125f);
                *(uint4*)(dst + p0 + 4 * j) = v;
            }
        }
    }

    float m[2][2], l[2][2], o[2][8][4];
#pragma unroll
    for (int mt = 0; mt < 2; mt++) {
        m[mt][0] = -1e30f; m[mt][1] = -1e30f;
        l[mt][0] = 0.f;    l[mt][1] = 0.f;
#pragma unroll
        for (int nt = 0; nt < 8; nt++)
#pragma unroll
            for (int c = 0; c < 4; c++) o[mt][nt][c] = 0.f;
    }

    const int rowg0 = 32 * w + g;
    const int kmax  = q0 + 64;

    for (int k0 = 0; k0 <= kmax; k0 += 64) {
        __syncthreads();
        // ---- load K (row-major pairs) and V (transposed pairs) ----
        {
            const float* kb = qkv + ((size_t)(b * T_SEQ + k0 + lr)) * C3 + C_DIM + h * DH;
            uint32_t* kd = Kh + lr * HP;
#pragma unroll
            for (int hs = 0; hs < 2; hs++) {
                const int c0 = colb + 32 * hs;
                const int p0 = (colb >> 1) + 16 * hs;
#pragma unroll
                for (int j = 0; j < 2; j++) {
                    float4 a = *(const float4*)(kb + c0 + 8 * j);
                    float4 bk = *(const float4*)(kb + c0 + 8 * j + 4);
                    uint4 v;
                    v.x = packh2(a.x, a.y);
                    v.y = packh2(a.z, a.w);
                    v.z = packh2(bk.x, bk.y);
                    v.w = packh2(bk.z, bk.w);
                    *(uint4*)(kd + p0 + 4 * j) = v;
                }
            }
            // V: tokens 2vr, 2vr+1, d = vds..vds+15 -> Vt[d][vr]
            const float* v0p = qkv + ((size_t)(b * T_SEQ + k0 + 2 * vr)) * C3 + 2 * C_DIM + h * DH + vds;
            const float* v1p = v0p + C3;
            float va[16], vb[16];
#pragma unroll
            for (int j = 0; j < 4; j++) {
                *(float4*)(va + 4 * j) = *(const float4*)(v0p + 4 * j);
                *(float4*)(vb + 4 * j) = *(const float4*)(v1p + 4 * j);
            }
#pragma unroll
            for (int i = 0; i < 16; i++)
                Vt[(vds + i) * HP + vr] = packh2(va[i], vb[i]);
        }
        __syncthreads();

        // ---- S = Q @ K^T : 4 k16 steps over d=64 ----
        float s[2][8][4];
#pragma unroll
        for (int mt = 0; mt < 2; mt++)
#pragma unroll
            for (int nt = 0; nt < 8; nt++)
#pragma unroll
                for (int c = 0; c < 4; c++) s[mt][nt][c] = 0.f;

#pragma unroll
        for (int ks = 0; ks < 4; ks++) {
            const int kp = ks * 8 + tg;
            uint32_t af[2][4];
#pragma unroll
            for (int mt = 0; mt < 2; mt++) {
                const int r = rowg0 + 16 * mt;
                af[mt][0] = Qh[(r    ) * HP + kp    ];
                af[mt][1] = Qh[(r + 8) * HP + kp    ];
                af[mt][2] = Qh[(r    ) * HP + kp + 4];
                af[mt][3] = Qh[(r + 8) * HP + kp + 4];
            }
#pragma unroll
            for (int nt = 0; nt < 8; nt++) {
                uint32_t bb[2];
                bb[0] = Kh[(nt * 8 + g) * HP + kp    ];
                bb[1] = Kh[(nt * 8 + g) * HP + kp + 4];
                mma_f16(s[0][nt], af[0], bb);
                mma_f16(s[1][nt], af[1], bb);
            }
        }

        // ---- causal mask (k0 >= q0 tiles) ----
        if (k0 >= q0) {
            const int dk = k0 - q0;
#pragma unroll
            for (int mt = 0; mt < 2; mt++) {
                const int r0 = rowg0 + 16 * mt;
#pragma unroll
                for (int nt = 0; nt < 8; nt++) {
                    const int c0 = nt * 8 + 2 * tg + dk;
                    if (c0     > r0    ) s[mt][nt][0] = -1e30f;
                    if (c0 + 1 > r0    ) s[mt][nt][1] = -1e30f;
                    if (c0     > r0 + 8) s[mt][nt][2] = -1e30f;
                    if (c0 + 1 > r0 + 8) s[mt][nt][3] = -1e30f;
                }
            }
        }

        // ---- online softmax (4 rows/thread, quad reductions) ----
#pragma unroll
        for (int mt = 0; mt < 2; mt++) {
            float mx0 = -1e30f, mx1 = -1e30f;
#pragma unroll
            for (int nt = 0; nt < 8; nt++) {
                mx0 = fmaxf(mx0, fmaxf(s[mt][nt][0], s[mt][nt][1]));
                mx1 = fmaxf(mx1, fmaxf(s[mt][nt][2], s[mt][nt][3]));
            }
            mx0 = fmaxf(mx0, __shfl_xor_sync(0xffffffffu, mx0, 1));
            mx0 = fmaxf(mx0, __shfl_xor_sync(0xffffffffu, mx0, 2));
            mx1 = fmaxf(mx1, __shfl_xor_sync(0xffffffffu, mx1, 1));
            mx1 = fmaxf(mx1, __shfl_xor_sync(0xffffffffu, mx1, 2));

            const float mn0 = fmaxf(m[mt][0], mx0);
            const float mn1 = fmaxf(m[mt][1], mx1);
            const float f0  = __expf(m[mt][0] - mn0);
            const float f1  = __expf(m[mt][1] - mn1);

            const int r0 = rowg0 + 16 * mt;
            float sum0 = 0.f, sum1 = 0.f;
#pragma unroll
            for (int nt = 0; nt < 8; nt++) {
                float p0 = __expf(s[mt][nt][0] - mn0);
                float p1 = __expf(s[mt][nt][1] - mn0);
                float p2 = __expf(s[mt][nt][2] - mn1);
                float p3 = __expf(s[mt][nt][3] - mn1);
                sum0 += p0 + p1;
                sum1 += p2 + p3;
                // packed P store: pair index nt*4 + tg
                Ph[(r0    ) * HP + nt * 4 + tg] = packh2(p0, p1);
                Ph[(r0 + 8) * HP + nt * 4 + tg] = packh2(p2, p3);
            }
            sum0 += __shfl_xor_sync(0xffffffffu, sum0, 1);
            sum0 += __shfl_xor_sync(0xffffffffu, sum0, 2);
            sum1 += __shfl_xor_sync(0xffffffffu, sum1, 1);
            sum1 += __shfl_xor_sync(0xffffffffu, sum1, 2);

            l[mt][0] = l[mt][0] * f0 + sum0;  m[mt][0] = mn0;
            l[mt][1] = l[mt][1] * f1 + sum1;  m[mt][1] = mn1;
#pragma unroll
            for (int nt = 0; nt < 8; nt++) {
                o[mt][nt][0] *= f0; o[mt][nt][1] *= f0;
                o[mt][nt][2] *= f1; o[mt][nt][3] *= f1;
            }
        }
        __syncwarp();

        // ---- O += P @ V : 4 k16 steps over keys=64 ----
#pragma unroll
        for (int ks = 0; ks < 4; ks++) {
            const int kp = ks * 8 + tg;
            uint32_t af[2][4];
#pragma unroll
            for (int mt = 0; mt < 2; mt++) {
                const int r = rowg0 + 16 * mt;
                af[mt][0] = Ph[(r    ) * HP + kp    ];
                af[mt][1] = Ph[(r + 8) * HP + kp    ];
                af[mt][2] = Ph[(r    ) * HP + kp + 4];
                af[mt][3] = Ph[(r + 8) * HP + kp + 4];
            }
#pragma unroll
            for (int nt = 0; nt < 8; nt++) {
                uint32_t bb[2];
                bb[0] = Vt[(nt * 8 + g) * HP + kp    ];
                bb[1] = Vt[(nt * 8 + g) * HP + kp + 4];
                mma_f16(o[0][nt], af[0], bb);
                mma_f16(o[1][nt], af[1], bb);
            }
        }
    }

    // ---- normalize, stage to smem as float (pitch 68 over Qh/Kh/Vt), write ----
    __syncthreads();
    float* Of = (float*)smu;   // [128][68]
#pragma unroll
    for (int mt = 0; mt < 2; mt++) {
        const int r0 = rowg0 + 16 * mt;
        const float inv0 = 1.f / l[mt][0];
        const float inv1 = 1.f / l[mt][1];
#pragma unroll
        for (int nt = 0; nt < 8; nt++) {
            float* d0 = Of + (r0    ) * 68 + nt * 8 + 2 * tg;
            float* d1 = Of + (r0 + 8) * 68 + nt * 8 + 2 * tg;
            d0[0] = o[mt][nt][0] * inv0; d0[1] = o[mt][nt][1] * inv0;
            d1[0] = o[mt][nt][2] * inv1; d1[1] = o[mt][nt][3] * inv1;
        }
    }
    __syncthreads();
#pragma unroll
    for (int rh = 0; rh < 2; rh++) {
        const int rr = lr + 64 * rh;
        const float* src = Of + rr * 68;
        float* dst = y + ((size_t)(b * T_SEQ + q0 + rr)) * C_DIM + h * DH;
#pragma unroll
        for (int hs = 0; hs < 2; hs++) {
            const int c0 = colb + 32 * hs;
#pragma unroll
            for (int j = 0; j < 4; j++)
                *(float4*)(dst + c0 + 4 * j) = *(const float4*)(src + c0 + 4 * j);
        }
    }
}

// ---------------------------------------------------------------------------
extern "C" void kernel_launch(void* const* d_in, const int* in_sizes, int n_in,
                              void* d_out, int out_size)
{
    const float* x     = (const float*)d_in[0];
    const float* Wqkv  = (const float*)d_in[1];
    const float* bqkv  = (const float*)d_in[2];
    const float* Wproj = (const float*)d_in[3];
    const float* bproj = (const float*)d_in[4];
    float* out = (float*)d_out;

    float *qkv, *y;
    cudaGetSymbolAddress((void**)&qkv, g_qkv);
    cudaGetSymbolAddress((void**)&y, g_y);

    cudaFuncSetAttribute(attn_mma_kernel,
                         cudaFuncAttributeMaxDynamicSharedMemorySize, ATTN_SMEM);

    // 1) QKV projection (tensor cores, FP16 -> FP32)
    f16_gemm_bias<<<dim3(C3 / GBN, M_ROWS / GBM), 256>>>(
        x, Wqkv, bqkv, qkv, M_ROWS, C3, C_DIM);

    // 2) causal attention (tensor cores, FP16 -> FP32)
    attn_mma_kernel<<<dim3(T_SEQ / 128, NH, B_SZ), 128, ATTN_SMEM>>>(qkv, y);

    // 3) output projection (tensor cores, FP16 -> FP32)
    f16_gemm_bias<<<dim3(C_DIM / GBN, M_ROWS / GBM), 256>>>(
        y, Wproj, bproj, out, M_ROWS, C_DIM, C_DIM);
}

// round 14
// speedup vs baseline: 1.5631x; 1.0478x over previous
#include <cuda_runtime.h>
#include <cuda_fp16.h>
#include <math.h>
#include <stdint.h>

// Shapes (fixed by the problem)
#define B_SZ   16
#define T_SEQ  1024
#define C_DIM  768
#define NH     12
#define DH     64
#define C3     2304       // 3*C
#define M_ROWS 16384      // B*T

// Scratch buffers (no cudaMalloc allowed)
__device__ float g_qkv[(size_t)M_ROWS * C3];   // [B*T, 3C]
__device__ float g_y[(size_t)M_ROWS * C_DIM];  // [B*T, C]

// ---------------------------------------------------------------------------
// Shared helpers
// ---------------------------------------------------------------------------
__device__ __forceinline__ uint32_t packh2(float a, float b) {
    __half2 h = __floats2half2_rn(a, b);
    return *(uint32_t*)&h;
}

__device__ __forceinline__ void mma_f16(float* c, const uint32_t* a, const uint32_t* b) {
    asm volatile(
        "mma.sync.aligned.m16n8k16.row.col.f32.f16.f16.f32 "
        "{%0,%1,%2,%3}, {%4,%5,%6,%7}, {%8,%9}, {%0,%1,%2,%3};"
        : "+f"(c[0]), "+f"(c[1]), "+f"(c[2]), "+f"(c[3])
        : "r"(a[0]), "r"(a[1]), "r"(a[2]), "r"(a[3]), "r"(b[0]), "r"(b[1]));
}

__device__ __forceinline__ void ldsm_x4(uint32_t* r, uint32_t addr) {
    asm volatile("ldmatrix.sync.aligned.m8n8.x4.shared.b16 {%0,%1,%2,%3}, [%4];"
                 : "=r"(r[0]), "=r"(r[1]), "=r"(r[2]), "=r"(r[3]) : "r"(addr));
}

// A-operand ldmatrix address (m16k16 tile): lanes 0-15 -> rows am+lane (halves 0-7
// window), lanes 16-31 -> rows am+(lane-16) at +4 words (halves 8-15).
// base_w = shared addr in BYTES of tile start; pitch/offsets in WORDS.
__device__ __forceinline__ uint32_t a_ldsm_addr(uint32_t base_b, int lane, int am,
                                                int pitch_w, int kp0_w) {
    return base_b + (uint32_t)(((am + (lane & 15)) * pitch_w + kp0_w + (lane >> 4) * 4) * 4);
}
// B-operand ldmatrix address (two n8k16 frags, rows bn0..bn0+15):
// lanes0-7 rows bn0+l @kp0 | lanes8-15 rows bn0+(l-8) @kp0+4 |
// lanes16-23 rows bn0+8+(l-16) @kp0 | lanes24-31 rows bn0+8+(l-24) @kp0+4.
__device__ __forceinline__ uint32_t b_ldsm_addr(uint32_t base_b, int lane, int bn0,
                                                int pitch_w, int kp0_w) {
    int row = bn0 + (lane & 7) + ((lane >> 4) << 3);
    int col = kp0_w + ((lane >> 3) & 1) * 4;
    return base_b + (uint32_t)((row * pitch_w + col) * 4);
}

// ---------------------------------------------------------------------------
// FP16 GEMM v7: same tiling as R12/R13 (CTA 256x128, 8 warps 4x2, warp 64x64,
// BK=32), fragments fed by ldmatrix.x4 instead of scalar LDS.
// ---------------------------------------------------------------------------
#define GBM 256
#define GBN 128
#define GBK 32
#define AP16 20
#define BP16 20

__global__ __launch_bounds__(256, 1) void f16_gemm_bias(
    const float* __restrict__ A, const float* __restrict__ B,
    const float* __restrict__ bias, float* __restrict__ C,
    int M, int N, int K)
{
    __shared__ uint32_t Asf[GBM * AP16];
    __shared__ uint32_t Bsf[GBN * BP16];

    const int tid  = threadIdx.x;
    const int wid  = tid >> 5;
    const int lane = tid & 31;
    const int wm   = wid >> 1;
    const int wn   = wid & 1;
    const int g    = lane >> 2;
    const int tg   = lane & 3;

    const uint32_t a_base = (uint32_t)__cvta_generic_to_shared(Asf);
    const uint32_t b_base = (uint32_t)__cvta_generic_to_shared(Bsf);

    const int ar = tid >> 3;
    const int ac = (tid & 7) * 4;
    const int bn_l = tid & 127;
    const int bkh  = (tid >> 7) * 8;

    const float* Ag = A + (size_t)(blockIdx.y * GBM + ar) * K + ac;
    const float* Bg = B + (size_t)(2 * bkh) * N + blockIdx.x * GBN + bn_l;

    float acc[4][8][4];
#pragma unroll
    for (int mt = 0; mt < 4; mt++)
#pragma unroll
        for (int nt = 0; nt < 8; nt++)
#pragma unroll
            for (int c = 0; c < 4; c++) acc[mt][nt][c] = 0.f;

    float4 pa[8];
    float  pbl[8], pbh[8];

#pragma unroll
    for (int i = 0; i < 8; i++) pa[i] = *(const float4*)(Ag + (size_t)(32 * i) * K);
#pragma unroll
    for (int i = 0; i < 8; i++) {
        pbl[i] = Bg[(size_t)(2 * i) * N];
        pbh[i] = Bg[(size_t)(2 * i + 1) * N];
    }
#pragma unroll
    for (int i = 0; i < 8; i++) {
        uint2 v = make_uint2(packh2(pa[i].x, pa[i].y), packh2(pa[i].z, pa[i].w));
        *(uint2*)&Asf[(ar + 32 * i) * AP16 + (ac >> 1)] = v;
        Bsf[bn_l * BP16 + bkh + i] = packh2(pbl[i], pbh[i]);
    }
    __syncthreads();

    for (int k0 = 0; k0 < K; k0 += GBK) {
        const bool has_next = (k0 + GBK) < K;
        if (has_next) {
#pragma unroll
            for (int i = 0; i < 8; i++)
                pa[i] = *(const float4*)(Ag + (size_t)(32 * i) * K + k0 + GBK);
#pragma unroll
            for (int i = 0; i < 8; i++) {
                pbl[i] = Bg[(size_t)(k0 + GBK + 2 * i) * N];
                pbh[i] = Bg[(size_t)(k0 + GBK + 2 * i + 1) * N];
            }
        }

#pragma unroll
        for (int ks = 0; ks < 2; ks++) {
            const int kp0 = ks * 8;
            uint32_t af[4][4], bf[8][2];
#pragma unroll
            for (int mt = 0; mt < 4; mt++)
                ldsm_x4(af[mt], a_ldsm_addr(a_base, lane, wm * 64 + mt * 16, AP16, kp0));
#pragma unroll
            for (int np = 0; np < 4; np++) {
                uint32_t r[4];
                ldsm_x4(r, b_ldsm_addr(b_base, lane, wn * 64 + np * 16, BP16, kp0));
                bf[2 * np][0] = r[0]; bf[2 * np][1] = r[1];
                bf[2 * np + 1][0] = r[2]; bf[2 * np + 1][1] = r[3];
            }
#pragma unroll
            for (int mt = 0; mt < 4; mt++)
#pragma unroll
                for (int nt = 0; nt < 8; nt++)
                    mma_f16(acc[mt][nt], af[mt], bf[nt]);
        }

        __syncthreads();
        if (has_next) {
#pragma unroll
            for (int i = 0; i < 8; i++) {
                uint2 v = make_uint2(packh2(pa[i].x, pa[i].y), packh2(pa[i].z, pa[i].w));
                *(uint2*)&Asf[(ar + 32 * i) * AP16 + (ac >> 1)] = v;
                Bsf[bn_l * BP16 + bkh + i] = packh2(pbl[i], pbh[i]);
            }
            __syncthreads();
        }
    }

    const int crow0 = blockIdx.y * GBM + wm * 64;
    const int ccol0 = blockIdx.x * GBN + wn * 64;
#pragma unroll
    for (int mt = 0; mt < 4; mt++) {
#pragma unroll
        for (int nt = 0; nt < 8; nt++) {
            const int row = crow0 + mt * 16 + g;
            const int col = ccol0 + nt * 8 + 2 * tg;
            const float b0 = bias[col], b1 = bias[col + 1];
            float2 v0 = make_float2(acc[mt][nt][0] + b0, acc[mt][nt][1] + b1);
            float2 v1 = make_float2(acc[mt][nt][2] + b0, acc[mt][nt][3] + b1);
            *(float2*)(C + (size_t)row * N + col)       = v0;
            *(float2*)(C + (size_t)(row + 8) * N + col) = v1;
        }
    }
}

// ---------------------------------------------------------------------------
// Flash-attention v5: FP16 mma + ldmatrix fragment feeds.
// q-tile 128, 4 warps; warp w owns rows 32w..32w+31 (mt=2 x 16-row).
// Smem (pitch HP=36): Qh[128], Kh[64], Vt[64] (d-major key-pairs), Ph[128].
// ---------------------------------------------------------------------------
#define HP 36
#define ATTN_SMEM ((128 + 64 + 64 + 128) * HP * 4)   // 55296 B

__global__ __launch_bounds__(128, 2) void attn_mma_kernel(
    const float* __restrict__ qkv, float* __restrict__ y)
{
    extern __shared__ uint32_t smu[];
    uint32_t* Qh = smu;                   // [128][HP]
    uint32_t* Kh = smu + 128 * HP;        // [64][HP]
    uint32_t* Vt = smu + 192 * HP;        // [64][HP]
    uint32_t* Ph = smu + 256 * HP;        // [128][HP]

    const uint32_t qh_base = (uint32_t)__cvta_generic_to_shared(Qh);
    const uint32_t kh_base = (uint32_t)__cvta_generic_to_shared(Kh);
    const uint32_t vt_base = (uint32_t)__cvta_generic_to_shared(Vt);
    const uint32_t ph_base = (uint32_t)__cvta_generic_to_shared(Ph);

    const int q0 = blockIdx.x * 128;
    const int h  = blockIdx.y;
    const int b  = blockIdx.z;

    const int tid  = threadIdx.x;
    const int w    = tid >> 5;
    const int lane = tid & 31;
    const int g    = lane >> 2;
    const int tg   = lane & 3;

    const int lr   = tid >> 1;            // 0..63
    const int colb = (tid & 1) * 16;      // 0 or 16
    const int vr   = tid & 31;            // token pair 0..31
    const int vds  = (tid >> 5) * 16;     // d base 0/16/32/48

    // ---- load Q tile (128 rows, scaled, packed half pairs) ----
#pragma unroll
    for (int rh = 0; rh < 2; rh++) {
        const int rr = lr + 64 * rh;
        const float* src = qkv + ((size_t)(b * T_SEQ + q0 + rr)) * C3 + h * DH;
        uint32_t* dst = Qh + rr * HP;
#pragma unroll
        for (int hs = 0; hs < 2; hs++) {
            const int c0 = colb + 32 * hs;
            const int p0 = (colb >> 1) + 16 * hs;
#pragma unroll
            for (int j = 0; j < 2; j++) {
                float4 a = *(const float4*)(src + c0 + 8 * j);
                float4 bq = *(const float4*)(src + c0 + 8 * j + 4);
                uint4 v;
                v.x = packh2(a.x * 0.125f, a.y * 0.125f);
                v.y = packh2(a.z * 0.125f, a.w * 0.125f);
                v.z = packh2(bq.x * 0.125f, bq.y * 0.125f);
                v.w = packh2(bq.z * 0.125f, bq.w * 0.125f);
                *(uint4*)(dst + p0 + 4 * j) = v;
            }
        }
    }

    float m[2][2], l[2][2], o[2][8][4];
#pragma unroll
    for (int mt = 0; mt < 2; mt++) {
        m[mt][0] = -1e30f; m[mt][1] = -1e30f;
        l[mt][0] = 0.f;    l[mt][1] = 0.f;
#pragma unroll
        for (int nt = 0; nt < 8; nt++)
#pragma unroll
            for (int c = 0; c < 4; c++) o[mt][nt][c] = 0.f;
    }

    const int rowg0 = 32 * w + g;
    const int kmax  = q0 + 64;

    for (int k0 = 0; k0 <= kmax; k0 += 64) {
        __syncthreads();
        // ---- load K (row-major pairs) and V (transposed pairs) ----
        {
            const float* kb = qkv + ((size_t)(b * T_SEQ + k0 + lr)) * C3 + C_DIM + h * DH;
            uint32_t* kd = Kh + lr * HP;
#pragma unroll
            for (int hs = 0; hs < 2; hs++) {
                const int c0 = colb + 32 * hs;
                const int p0 = (colb >> 1) + 16 * hs;
#pragma unroll
                for (int j = 0; j < 2; j++) {
                    float4 a = *(const float4*)(kb + c0 + 8 * j);
                    float4 bk = *(const float4*)(kb + c0 + 8 * j + 4);
                    uint4 v;
                    v.x = packh2(a.x, a.y);
                    v.y = packh2(a.z, a.w);
                    v.z = packh2(bk.x, bk.y);
                    v.w = packh2(bk.z, bk.w);
                    *(uint4*)(kd + p0 + 4 * j) = v;
                }
            }
            const float* v0p = qkv + ((size_t)(b * T_SEQ + k0 + 2 * vr)) * C3 + 2 * C_DIM + h * DH + vds;
            const float* v1p = v0p + C3;
            float va[16], vb[16];
#pragma unroll
            for (int j = 0; j < 4; j++) {
                *(float4*)(va + 4 * j) = *(const float4*)(v0p + 4 * j);
                *(float4*)(vb + 4 * j) = *(const float4*)(v1p + 4 * j);
            }
#pragma unroll
            for (int i = 0; i < 16; i++)
                Vt[(vds + i) * HP + vr] = packh2(va[i], vb[i]);
        }
        __syncthreads();

        // ---- S = Q @ K^T : 4 k16 steps over d=64 ----
        float s[2][8][4];
#pragma unroll
        for (int mt = 0; mt < 2; mt++)
#pragma unroll
            for (int nt = 0; nt < 8; nt++)
#pragma unroll
                for (int c = 0; c < 4; c++) s[mt][nt][c] = 0.f;

#pragma unroll
        for (int ks = 0; ks < 4; ks++) {
            const int kp0 = ks * 8;
            uint32_t af[2][4], bf[8][2];
#pragma unroll
            for (int mt = 0; mt < 2; mt++)
                ldsm_x4(af[mt], a_ldsm_addr(qh_base, lane, 32 * w + 16 * mt, HP, kp0));
#pragma unroll
            for (int np = 0; np < 4; np++) {
                uint32_t r[4];
                ldsm_x4(r, b_ldsm_addr(kh_base, lane, np * 16, HP, kp0));
                bf[2 * np][0] = r[0]; bf[2 * np][1] = r[1];
                bf[2 * np + 1][0] = r[2]; bf[2 * np + 1][1] = r[3];
            }
#pragma unroll
            for (int nt = 0; nt < 8; nt++) {
                mma_f16(s[0][nt], af[0], bf[nt]);
                mma_f16(s[1][nt], af[1], bf[nt]);
            }
        }

        // ---- causal mask (k0 >= q0 tiles) ----
        if (k0 >= q0) {
            const int dk = k0 - q0;
#pragma unroll
            for (int mt = 0; mt < 2; mt++) {
                const int r0 = rowg0 + 16 * mt;
#pragma unroll
                for (int nt = 0; nt < 8; nt++) {
                    const int c0 = nt * 8 + 2 * tg + dk;
                    if (c0     > r0    ) s[mt][nt][0] = -1e30f;
                    if (c0 + 1 > r0    ) s[mt][nt][1] = -1e30f;
                    if (c0     > r0 + 8) s[mt][nt][2] = -1e30f;
                    if (c0 + 1 > r0 + 8) s[mt][nt][3] = -1e30f;
                }
            }
        }

        // ---- online softmax (4 rows/thread, quad reductions) ----
#pragma unroll
        for (int mt = 0; mt < 2; mt++) {
            float mx0 = -1e30f, mx1 = -1e30f;
#pragma unroll
            for (int nt = 0; nt < 8; nt++) {
                mx0 = fmaxf(mx0, fmaxf(s[mt][nt][0], s[mt][nt][1]));
                mx1 = fmaxf(mx1, fmaxf(s[mt][nt][2], s[mt][nt][3]));
            }
            mx0 = fmaxf(mx0, __shfl_xor_sync(0xffffffffu, mx0, 1));
            mx0 = fmaxf(mx0, __shfl_xor_sync(0xffffffffu, mx0, 2));
            mx1 = fmaxf(mx1, __shfl_xor_sync(0xffffffffu, mx1, 1));
            mx1 = fmaxf(mx1, __shfl_xor_sync(0xffffffffu, mx1, 2));

            const float mn0 = fmaxf(m[mt][0], mx0);
            const float mn1 = fmaxf(m[mt][1], mx1);
            const float f0  = __expf(m[mt][0] - mn0);
            const float f1  = __expf(m[mt][1] - mn1);

            const int r0 = rowg0 + 16 * mt;
            float sum0 = 0.f, sum1 = 0.f;
#pragma unroll
            for (int nt = 0; nt < 8; nt++) {
                float p0 = __expf(s[mt][nt][0] - mn0);
                float p1 = __expf(s[mt][nt][1] - mn0);
                float p2 = __expf(s[mt][nt][2] - mn1);
                float p3 = __expf(s[mt][nt][3] - mn1);
                sum0 += p0 + p1;
                sum1 += p2 + p3;
                Ph[(r0    ) * HP + nt * 4 + tg] = packh2(p0, p1);
                Ph[(r0 + 8) * HP + nt * 4 + tg] = packh2(p2, p3);
            }
            sum0 += __shfl_xor_sync(0xffffffffu, sum0, 1);
            sum0 += __shfl_xor_sync(0xffffffffu, sum0, 2);
            sum1 += __shfl_xor_sync(0xffffffffu, sum1, 1);
            sum1 += __shfl_xor_sync(0xffffffffu, sum1, 2);

            l[mt][0] = l[mt][0] * f0 + sum0;  m[mt][0] = mn0;
            l[mt][1] = l[mt][1] * f1 + sum1;  m[mt][1] = mn1;
#pragma unroll
            for (int nt = 0; nt < 8; nt++) {
                o[mt][nt][0] *= f0; o[mt][nt][1] *= f0;
                o[mt][nt][2] *= f1; o[mt][nt][3] *= f1;
            }
        }
        __syncwarp();

        // ---- O += P @ V : 4 k16 steps over keys=64 ----
#pragma unroll
        for (int ks = 0; ks < 4; ks++) {
            const int kp0 = ks * 8;
            uint32_t af[2][4], bf[8][2];
#pragma unroll
            for (int mt = 0; mt < 2; mt++)
                ldsm_x4(af[mt], a_ldsm_addr(ph_base, lane, 32 * w + 16 * mt, HP, kp0));
#pragma unroll
            for (int np = 0; np < 4; np++) {
                uint32_t r[4];
                ldsm_x4(r, b_ldsm_addr(vt_base, lane, np * 16, HP, kp0));
                bf[2 * np][0] = r[0]; bf[2 * np][1] = r[1];
                bf[2 * np + 1][0] = r[2]; bf[2 * np + 1][1] = r[3];
            }
#pragma unroll
            for (int nt = 0; nt < 8; nt++) {
                mma_f16(o[0][nt], af[0], bf[nt]);
                mma_f16(o[1][nt], af[1], bf[nt]);
            }
        }
    }

    // ---- normalize, stage to smem as float (pitch 68 over Qh/Kh/Vt), write ----
    __syncthreads();
    float* Of = (float*)smu;   // [128][68]
#pragma unroll
    for (int mt = 0; mt < 2; mt++) {
        const int r0 = rowg0 + 16 * mt;
        const float inv0 = 1.f / l[mt][0];
        const float inv1 = 1.f / l[mt][1];
#pragma unroll
        for (int nt = 0; nt < 8; nt++) {
            float* d0 = Of + (r0    ) * 68 + nt * 8 + 2 * tg;
            float* d1 = Of + (r0 + 8) * 68 + nt * 8 + 2 * tg;
            d0[0] = o[mt][nt][0] * inv0; d0[1] = o[mt][nt][1] * inv0;
            d1[0] = o[mt][nt][2] * inv1; d1[1] = o[mt][nt][3] * inv1;
        }
    }
    __syncthreads();
#pragma unroll
    for (int rh = 0; rh < 2; rh++) {
        const int rr = lr + 64 * rh;
        const float* src = Of + rr * 68;
        float* dst = y + ((size_t)(b * T_SEQ + q0 + rr)) * C_DIM + h * DH;
#pragma unroll
        for (int hs = 0; hs < 2; hs++) {
            const int c0 = colb + 32 * hs;
#pragma unroll
            for (int j = 0; j < 4; j++)
                *(float4*)(dst + c0 + 4 * j) = *(const float4*)(src + c0 + 4 * j);
        }
    }
}

// ---------------------------------------------------------------------------
extern "C" void kernel_launch(void* const* d_in, const int* in_sizes, int n_in,
                              void* d_out, int out_size)
{
    const float* x     = (const float*)d_in[0];
    const float* Wqkv  = (const float*)d_in[1];
    const float* bqkv  = (const float*)d_in[2];
    const float* Wproj = (const float*)d_in[3];
    const float* bproj = (const float*)d_in[4];
    float* out = (float*)d_out;

    float *qkv, *y;
    cudaGetSymbolAddress((void**)&qkv, g_qkv);
    cudaGetSymbolAddress((void**)&y, g_y);

    cudaFuncSetAttribute(attn_mma_kernel,
                         cudaFuncAttributeMaxDynamicSharedMemorySize, ATTN_SMEM);

    // 1) QKV projection (tensor cores, FP16 -> FP32)
    f16_gemm_bias<<<dim3(C3 / GBN, M_ROWS / GBM), 256>>>(
        x, Wqkv, bqkv, qkv, M_ROWS, C3, C_DIM);

    // 2) causal attention (tensor cores, FP16 -> FP32)
    attn_mma_kernel<<<dim3(T_SEQ / 128, NH, B_SZ), 128, ATTN_SMEM>>>(qkv, y);

    // 3) output projection (tensor cores, FP16 -> FP32)
    f16_gemm_bias<<<dim3(C_DIM / GBN, M_ROWS / GBM), 256>>>(
        y, Wproj, bproj, out, M_ROWS, C_DIM, C_DIM);
}

// round 15
// speedup vs baseline: 1.7961x; 1.1491x over previous
#include <cuda_runtime.h>
#include <cuda_fp16.h>
#include <math.h>
#include <stdint.h>

// Shapes (fixed by the problem)
#define B_SZ   16
#define T_SEQ  1024
#define C_DIM  768
#define NH     12
#define DH     64
#define C3     2304       // 3*C
#define M_ROWS 16384      // B*T

// Scratch buffers (no cudaMalloc allowed) — fp16 storage end-to-end
__device__ __half g_xh[(size_t)M_ROWS * C_DIM];     // x in fp16
__device__ __half g_qkv_h[(size_t)M_ROWS * C3];     // qkv in fp16
__device__ __half g_y_h[(size_t)M_ROWS * C_DIM];    // attention out fp16
__device__ __half g_wt_qkv[(size_t)C3 * C_DIM];     // W_qkv^T [2304][768] fp16
__device__ __half g_wt_proj[(size_t)C_DIM * C_DIM]; // W_proj^T [768][768] fp16

// ---------------------------------------------------------------------------
// Helpers
// ---------------------------------------------------------------------------
__device__ __forceinline__ uint32_t packh2(float a, float b) {
    __half2 h = __floats2half2_rn(a, b);
    return *(uint32_t*)&h;
}
__device__ __forceinline__ void mma_f16(float* c, const uint32_t* a, const uint32_t* b) {
    asm volatile(
        "mma.sync.aligned.m16n8k16.row.col.f32.f16.f16.f32 "
        "{%0,%1,%2,%3}, {%4,%5,%6,%7}, {%8,%9}, {%0,%1,%2,%3};"
        : "+f"(c[0]), "+f"(c[1]), "+f"(c[2]), "+f"(c[3])
        : "r"(a[0]), "r"(a[1]), "r"(a[2]), "r"(a[3]), "r"(b[0]), "r"(b[1]));
}
__device__ __forceinline__ void ldsm_x4(uint32_t* r, uint32_t addr) {
    asm volatile("ldmatrix.sync.aligned.m8n8.x4.shared.b16 {%0,%1,%2,%3}, [%4];"
                 : "=r"(r[0]), "=r"(r[1]), "=r"(r[2]), "=r"(r[3]) : "r"(addr));
}
__device__ __forceinline__ uint32_t a_ldsm_addr(uint32_t base_b, int lane, int am,
                                                int pitch_w, int kp0_w) {
    return base_b + (uint32_t)(((am + (lane & 15)) * pitch_w + kp0_w + (lane >> 4) * 4) * 4);
}
__device__ __forceinline__ uint32_t b_ldsm_addr(uint32_t base_b, int lane, int bn0,
                                                int pitch_w, int kp0_w) {
    int row = bn0 + (lane & 7) + ((lane >> 4) << 3);
    int col = kp0_w + ((lane >> 3) & 1) * 4;
    return base_b + (uint32_t)((row * pitch_w + col) * 4);
}

// ---------------------------------------------------------------------------
// Pre-pass: fp32 -> fp16 convert, and convert+transpose for weights
// ---------------------------------------------------------------------------
__global__ void cvt_f2h(const float* __restrict__ in, __half* __restrict__ out, int n4)
{
    int i = blockIdx.x * blockDim.x + threadIdx.x;
    if (i < n4) {
        float4 v = *(const float4*)(in + 4 * (size_t)i);
        uint2 o;
        o.x = packh2(v.x, v.y);
        o.y = packh2(v.z, v.w);
        *(uint2*)(out + 4 * (size_t)i) = o;
    }
}

// out[C][R] = (half)in[R][C]
__global__ void tcvt(const float* __restrict__ in, __half* __restrict__ out, int R, int C)
{
    __shared__ float t[32][33];
    const int bx = blockIdx.x * 32;   // col tile
    const int by = blockIdx.y * 32;   // row tile
#pragma unroll
    for (int j = threadIdx.y; j < 32; j += 8)
        t[j][threadIdx.x] = in[(size_t)(by + j) * C + bx + threadIdx.x];
    __syncthreads();
#pragma unroll
    for (int j = threadIdx.y; j < 32; j += 8)
        out[(size_t)(bx + j) * R + by + threadIdx.x] = __float2half(t[threadIdx.x][j]);
}

// ---------------------------------------------------------------------------
// FP16 GEMM v8: C = A[M,K] @ Bt[N,K]^T + bias[N].
// A, Bt are fp16 (k-contiguous); no conversion in the hot loop.
// CTA 256x128, 8 warps (4x2), warp tile 64x64, BK=32, ldmatrix feeds.
// halfOut: write fp16 (qkv) or fp32 (final out).
// ---------------------------------------------------------------------------
#define GBM 256
#define GBN 128
#define GBK 32
#define AP16 20
#define BP16 20

__global__ __launch_bounds__(256, 1) void f16_gemm_bias(
    const __half* __restrict__ A, const __half* __restrict__ Bt,
    const float* __restrict__ bias, void* __restrict__ Cv,
    int M, int N, int K, int halfOut)
{
    __shared__ uint32_t Asf[GBM * AP16];
    __shared__ uint32_t Bsf[GBN * BP16];

    const int tid  = threadIdx.x;
    const int wid  = tid >> 5;
    const int lane = tid & 31;
    const int wm   = wid >> 1;
    const int wn   = wid & 1;
    const int g    = lane >> 2;
    const int tg   = lane & 3;

    const uint32_t a_base = (uint32_t)__cvta_generic_to_shared(Asf);
    const uint32_t b_base = (uint32_t)__cvta_generic_to_shared(Bsf);

    // loaders: 8 threads per row, 4 halfs (uint2) each
    const int ar = tid >> 3;            // 0..31
    const int ac = (tid & 7) * 4;       // half col 0..28
    const int aw = ac >> 1;             // word col

    const __half* Ag = A  + (size_t)(blockIdx.y * GBM + ar) * K + ac;
    const __half* Bg = Bt + (size_t)(blockIdx.x * GBN + ar) * K + ac;

    float acc[4][8][4];
#pragma unroll
    for (int mt = 0; mt < 4; mt++)
#pragma unroll
        for (int nt = 0; nt < 8; nt++)
#pragma unroll
            for (int c = 0; c < 4; c++) acc[mt][nt][c] = 0.f;

    uint2 pa[8], pb[4];
#pragma unroll
    for (int i = 0; i < 8; i++) pa[i] = *(const uint2*)(Ag + (size_t)(32 * i) * K);
#pragma unroll
    for (int j = 0; j < 4; j++) pb[j] = *(const uint2*)(Bg + (size_t)(32 * j) * K);
#pragma unroll
    for (int i = 0; i < 8; i++) *(uint2*)&Asf[(ar + 32 * i) * AP16 + aw] = pa[i];
#pragma unroll
    for (int j = 0; j < 4; j++) *(uint2*)&Bsf[(ar + 32 * j) * BP16 + aw] = pb[j];
    __syncthreads();

    for (int k0 = 0; k0 < K; k0 += GBK) {
        const bool has_next = (k0 + GBK) < K;
        if (has_next) {
#pragma unroll
            for (int i = 0; i < 8; i++)
                pa[i] = *(const uint2*)(Ag + (size_t)(32 * i) * K + k0 + GBK);
#pragma unroll
            for (int j = 0; j < 4; j++)
                pb[j] = *(const uint2*)(Bg + (size_t)(32 * j) * K + k0 + GBK);
        }

#pragma unroll
        for (int ks = 0; ks < 2; ks++) {
            const int kp0 = ks * 8;
            uint32_t af[4][4], bf[8][2];
#pragma unroll
            for (int mt = 0; mt < 4; mt++)
                ldsm_x4(af[mt], a_ldsm_addr(a_base, lane, wm * 64 + mt * 16, AP16, kp0));
#pragma unroll
            for (int np = 0; np < 4; np++) {
                uint32_t r[4];
                ldsm_x4(r, b_ldsm_addr(b_base, lane, wn * 64 + np * 16, BP16, kp0));
                bf[2 * np][0] = r[0]; bf[2 * np][1] = r[1];
                bf[2 * np + 1][0] = r[2]; bf[2 * np + 1][1] = r[3];
            }
#pragma unroll
            for (int mt = 0; mt < 4; mt++)
#pragma unroll
                for (int nt = 0; nt < 8; nt++)
                    mma_f16(acc[mt][nt], af[mt], bf[nt]);
        }

        __syncthreads();
        if (has_next) {
#pragma unroll
            for (int i = 0; i < 8; i++) *(uint2*)&Asf[(ar + 32 * i) * AP16 + aw] = pa[i];
#pragma unroll
            for (int j = 0; j < 4; j++) *(uint2*)&Bsf[(ar + 32 * j) * BP16 + aw] = pb[j];
            __syncthreads();
        }
    }

    const int crow0 = blockIdx.y * GBM + wm * 64;
    const int ccol0 = blockIdx.x * GBN + wn * 64;
    if (halfOut) {
        __half* Ch = (__half*)Cv;
#pragma unroll
        for (int mt = 0; mt < 4; mt++) {
#pragma unroll
            for (int nt = 0; nt < 8; nt++) {
                const int row = crow0 + mt * 16 + g;
                const int col = ccol0 + nt * 8 + 2 * tg;
                const float b0 = bias[col], b1 = bias[col + 1];
                *(uint32_t*)(Ch + (size_t)row * N + col) =
                    packh2(acc[mt][nt][0] + b0, acc[mt][nt][1] + b1);
                *(uint32_t*)(Ch + (size_t)(row + 8) * N + col) =
                    packh2(acc[mt][nt][2] + b0, acc[mt][nt][3] + b1);
            }
        }
    } else {
        float* Cf = (float*)Cv;
#pragma unroll
        for (int mt = 0; mt < 4; mt++) {
#pragma unroll
            for (int nt = 0; nt < 8; nt++) {
                const int row = crow0 + mt * 16 + g;
                const int col = ccol0 + nt * 8 + 2 * tg;
                const float b0 = bias[col], b1 = bias[col + 1];
                *(float2*)(Cf + (size_t)row * N + col) =
                    make_float2(acc[mt][nt][0] + b0, acc[mt][nt][1] + b1);
                *(float2*)(Cf + (size_t)(row + 8) * N + col) =
                    make_float2(acc[mt][nt][2] + b0, acc[mt][nt][3] + b1);
            }
        }
    }
}

// ---------------------------------------------------------------------------
// Flash-attention v6: fp16 in/out, fp16 mma, ldmatrix feeds.
// q-tile 128, 4 warps; warp w owns rows 32w..32w+31 (mt=2 x 16-row).
// Smem (pitch HP=36 words): Qh[128], Kh[64], Vt[64], Ph[128].
// ---------------------------------------------------------------------------
#define HP 36
#define ATTN_SMEM ((128 + 64 + 64 + 128) * HP * 4)   // 55296 B

__global__ __launch_bounds__(128, 2) void attn_mma_kernel(
    const __half* __restrict__ qkv, __half* __restrict__ y)
{
    extern __shared__ uint32_t smu[];
    uint32_t* Qh = smu;                   // [128][HP]
    uint32_t* Kh = smu + 128 * HP;        // [64][HP]
    uint32_t* Vt = smu + 192 * HP;        // [64][HP]
    uint32_t* Ph = smu + 256 * HP;        // [128][HP]

    const uint32_t qh_base = (uint32_t)__cvta_generic_to_shared(Qh);
    const uint32_t kh_base = (uint32_t)__cvta_generic_to_shared(Kh);
    const uint32_t vt_base = (uint32_t)__cvta_generic_to_shared(Vt);
    const uint32_t ph_base = (uint32_t)__cvta_generic_to_shared(Ph);

    const int q0 = blockIdx.x * 128;
    const int h  = blockIdx.y;
    const int b  = blockIdx.z;

    const int tid  = threadIdx.x;
    const int w    = tid >> 5;
    const int lane = tid & 31;
    const int g    = lane >> 2;
    const int tg   = lane & 3;

    const int lr = tid >> 1;              // 0..63
    const int hc = (tid & 1) * 32;        // half col base: 0 or 32
    const int hw = hc >> 1;               // word base: 0 or 16
    const int vr   = tid & 31;            // token pair 0..31
    const int vds  = (tid >> 5) * 16;     // d base 0/16/32/48

    const uint32_t sc = packh2(0.125f, 0.125f);
    const __half2 scale2 = *(const __half2*)&sc;

    // ---- load Q tile (128 rows, scaled) ----
#pragma unroll
    for (int rh = 0; rh < 2; rh++) {
        const int rr = lr + 64 * rh;
        const __half* src = qkv + ((size_t)(b * T_SEQ + q0 + rr)) * C3 + h * DH + hc;
        uint32_t* dst = Qh + rr * HP + hw;
#pragma unroll
        for (int j = 0; j < 4; j++) {
            uint4 v = *(const uint4*)(src + 8 * j);
            __half2* hv = (__half2*)&v;
            hv[0] = __hmul2(hv[0], scale2);
            hv[1] = __hmul2(hv[1], scale2);
            hv[2] = __hmul2(hv[2], scale2);
            hv[3] = __hmul2(hv[3], scale2);
            *(uint4*)(dst + 4 * j) = v;
        }
    }

    float m[2][2], l[2][2], o[2][8][4];
#pragma unroll
    for (int mt = 0; mt < 2; mt++) {
        m[mt][0] = -1e30f; m[mt][1] = -1e30f;
        l[mt][0] = 0.f;    l[mt][1] = 0.f;
#pragma unroll
        for (int nt = 0; nt < 8; nt++)
#pragma unroll
            for (int c = 0; c < 4; c++) o[mt][nt][c] = 0.f;
    }

    const int rowg0 = 32 * w + g;
    const int kmax  = q0 + 64;

    for (int k0 = 0; k0 <= kmax; k0 += 64) {
        __syncthreads();
        // ---- load K (direct uint4 copies) and V (byte_perm transpose) ----
        {
            const __half* kb = qkv + ((size_t)(b * T_SEQ + k0 + lr)) * C3 + C_DIM + h * DH + hc;
            uint32_t* kd = Kh + lr * HP + hw;
#pragma unroll
            for (int j = 0; j < 4; j++)
                *(uint4*)(kd + 4 * j) = *(const uint4*)(kb + 8 * j);

            const __half* v0p = qkv + ((size_t)(b * T_SEQ + k0 + 2 * vr)) * C3 + 2 * C_DIM + h * DH + vds;
            const __half* v1p = v0p + C3;
            uint32_t u0[8], u1[8];
            *(uint4*)(u0    ) = *(const uint4*)(v0p);
            *(uint4*)(u0 + 4) = *(const uint4*)(v0p + 8);
            *(uint4*)(u1    ) = *(const uint4*)(v1p);
            *(uint4*)(u1 + 4) = *(const uint4*)(v1p + 8);
#pragma unroll
            for (int i = 0; i < 8; i++) {
                Vt[(vds + 2 * i    ) * HP + vr] = __byte_perm(u0[i], u1[i], 0x5410);
                Vt[(vds + 2 * i + 1) * HP + vr] = __byte_perm(u0[i], u1[i], 0x7632);
            }
        }
        __syncthreads();

        // ---- S = Q @ K^T : 4 k16 steps over d=64 ----
        float s[2][8][4];
#pragma unroll
        for (int mt = 0; mt < 2; mt++)
#pragma unroll
            for (int nt = 0; nt < 8; nt++)
#pragma unroll
                for (int c = 0; c < 4; c++) s[mt][nt][c] = 0.f;

#pragma unroll
        for (int ks = 0; ks < 4; ks++) {
            const int kp0 = ks * 8;
            uint32_t af[2][4], bf[8][2];
#pragma unroll
            for (int mt = 0; mt < 2; mt++)
                ldsm_x4(af[mt], a_ldsm_addr(qh_base, lane, 32 * w + 16 * mt, HP, kp0));
#pragma unroll
            for (int np = 0; np < 4; np++) {
                uint32_t r[4];
                ldsm_x4(r, b_ldsm_addr(kh_base, lane, np * 16, HP, kp0));
                bf[2 * np][0] = r[0]; bf[2 * np][1] = r[1];
                bf[2 * np + 1][0] = r[2]; bf[2 * np + 1][1] = r[3];
            }
#pragma unroll
            for (int nt = 0; nt < 8; nt++) {
                mma_f16(s[0][nt], af[0], bf[nt]);
                mma_f16(s[1][nt], af[1], bf[nt]);
            }
        }

        // ---- causal mask (k0 >= q0 tiles) ----
        if (k0 >= q0) {
            const int dk = k0 - q0;
#pragma unroll
            for (int mt = 0; mt < 2; mt++) {
                const int r0 = rowg0 + 16 * mt;
#pragma unroll
                for (int nt = 0; nt < 8; nt++) {
                    const int c0 = nt * 8 + 2 * tg + dk;
                    if (c0     > r0    ) s[mt][nt][0] = -1e30f;
                    if (c0 + 1 > r0    ) s[mt][nt][1] = -1e30f;
                    if (c0     > r0 + 8) s[mt][nt][2] = -1e30f;
                    if (c0 + 1 > r0 + 8) s[mt][nt][3] = -1e30f;
                }
            }
        }

        // ---- online softmax ----
#pragma unroll
        for (int mt = 0; mt < 2; mt++) {
            float mx0 = -1e30f, mx1 = -1e30f;
#pragma unroll
            for (int nt = 0; nt < 8; nt++) {
                mx0 = fmaxf(mx0, fmaxf(s[mt][nt][0], s[mt][nt][1]));
                mx1 = fmaxf(mx1, fmaxf(s[mt][nt][2], s[mt][nt][3]));
            }
            mx0 = fmaxf(mx0, __shfl_xor_sync(0xffffffffu, mx0, 1));
            mx0 = fmaxf(mx0, __shfl_xor_sync(0xffffffffu, mx0, 2));
            mx1 = fmaxf(mx1, __shfl_xor_sync(0xffffffffu, mx1, 1));
            mx1 = fmaxf(mx1, __shfl_xor_sync(0xffffffffu, mx1, 2));

            const float mn0 = fmaxf(m[mt][0], mx0);
            const float mn1 = fmaxf(m[mt][1], mx1);
            const float f0  = __expf(m[mt][0] - mn0);
            const float f1  = __expf(m[mt][1] - mn1);

            const int r0 = rowg0 + 16 * mt;
            float sum0 = 0.f, sum1 = 0.f;
#pragma unroll
            for (int nt = 0; nt < 8; nt++) {
                float p0 = __expf(s[mt][nt][0] - mn0);
                float p1 = __expf(s[mt][nt][1] - mn0);
                float p2 = __expf(s[mt][nt][2] - mn1);
                float p3 = __expf(s[mt][nt][3] - mn1);
                sum0 += p0 + p1;
                sum1 += p2 + p3;
                Ph[(r0    ) * HP + nt * 4 + tg] = packh2(p0, p1);
                Ph[(r0 + 8) * HP + nt * 4 + tg] = packh2(p2, p3);
            }
            sum0 += __shfl_xor_sync(0xffffffffu, sum0, 1);
            sum0 += __shfl_xor_sync(0xffffffffu, sum0, 2);
            sum1 += __shfl_xor_sync(0xffffffffu, sum1, 1);
            sum1 += __shfl_xor_sync(0xffffffffu, sum1, 2);

            l[mt][0] = l[mt][0] * f0 + sum0;  m[mt][0] = mn0;
            l[mt][1] = l[mt][1] * f1 + sum1;  m[mt][1] = mn1;
#pragma unroll
            for (int nt = 0; nt < 8; nt++) {
                o[mt][nt][0] *= f0; o[mt][nt][1] *= f0;
                o[mt][nt][2] *= f1; o[mt][nt][3] *= f1;
            }
        }
        __syncwarp();

        // ---- O += P @ V ----
#pragma unroll
        for (int ks = 0; ks < 4; ks++) {
            const int kp0 = ks * 8;
            uint32_t af[2][4], bf[8][2];
#pragma unroll
            for (int mt = 0; mt < 2; mt++)
                ldsm_x4(af[mt], a_ldsm_addr(ph_base, lane, 32 * w + 16 * mt, HP, kp0));
#pragma unroll
            for (int np = 0; np < 4; np++) {
                uint32_t r[4];
                ldsm_x4(r, b_ldsm_addr(vt_base, lane, np * 16, HP, kp0));
                bf[2 * np][0] = r[0]; bf[2 * np][1] = r[1];
                bf[2 * np + 1][0] = r[2]; bf[2 * np + 1][1] = r[3];
            }
#pragma unroll
            for (int nt = 0; nt < 8; nt++) {
                mma_f16(o[0][nt], af[0], bf[nt]);
                mma_f16(o[1][nt], af[1], bf[nt]);
            }
        }
    }

    // ---- normalize, stage as fp16 pairs (reuse Qh region), coalesced write ----
    __syncthreads();
    uint32_t* Of = smu;   // [128][HP] half-pairs
#pragma unroll
    for (int mt = 0; mt < 2; mt++) {
        const int r0 = rowg0 + 16 * mt;
        const float inv0 = 1.f / l[mt][0];
        const float inv1 = 1.f / l[mt][1];
#pragma unroll
        for (int nt = 0; nt < 8; nt++) {
            Of[(r0    ) * HP + nt * 4 + tg] = packh2(o[mt][nt][0] * inv0, o[mt][nt][1] * inv0);
            Of[(r0 + 8) * HP + nt * 4 + tg] = packh2(o[mt][nt][2] * inv1, o[mt][nt][3] * inv1);
        }
    }
    __syncthreads();
#pragma unroll
    for (int rh = 0; rh < 2; rh++) {
        const int rr = lr + 64 * rh;
        const uint32_t* src = Of + rr * HP + hw;
        __half* dst = y + ((size_t)(b * T_SEQ + q0 + rr)) * C_DIM + h * DH + hc;
#pragma unroll
        for (int j = 0; j < 4; j++)
            *(uint4*)(dst + 8 * j) = *(const uint4*)(src + 4 * j);
    }
}

// ---------------------------------------------------------------------------
extern "C" void kernel_launch(void* const* d_in, const int* in_sizes, int n_in,
                              void* d_out, int out_size)
{
    const float* x     = (const float*)d_in[0];
    const float* Wqkv  = (const float*)d_in[1];
    const float* bqkv  = (const float*)d_in[2];
    const float* Wproj = (const float*)d_in[3];
    const float* bproj = (const float*)d_in[4];
    float* out = (float*)d_out;

    __half *xh, *qkvh, *yh, *wtq, *wtp;
    cudaGetSymbolAddress((void**)&xh, g_xh);
    cudaGetSymbolAddress((void**)&qkvh, g_qkv_h);
    cudaGetSymbolAddress((void**)&yh, g_y_h);
    cudaGetSymbolAddress((void**)&wtq, g_wt_qkv);
    cudaGetSymbolAddress((void**)&wtp, g_wt_proj);

    cudaFuncSetAttribute(attn_mma_kernel,
                         cudaFuncAttributeMaxDynamicSharedMemorySize, ATTN_SMEM);

    // 0) pre-pass: x -> fp16; weights -> fp16 transposed [N][K]
    {
        const int n4 = (M_ROWS * C_DIM) / 4;
        cvt_f2h<<<(n4 + 255) / 256, 256>>>(x, xh, n4);
        tcvt<<<dim3(C3 / 32, C_DIM / 32), dim3(32, 8)>>>(Wqkv, wtq, C_DIM, C3);
        tcvt<<<dim3(C_DIM / 32, C_DIM / 32), dim3(32, 8)>>>(Wproj, wtp, C_DIM, C_DIM);
    }

    // 1) QKV projection (fp16 in, fp16 out)
    f16_gemm_bias<<<dim3(C3 / GBN, M_ROWS / GBM), 256>>>(
        xh, wtq, bqkv, qkvh, M_ROWS, C3, C_DIM, 1);

    // 2) causal attention (fp16 in, fp16 out)
    attn_mma_kernel<<<dim3(T_SEQ / 128, NH, B_SZ), 128, ATTN_SMEM>>>(qkvh, yh);

    // 3) output projection (fp16 in, fp32 out)
    f16_gemm_bias<<<dim3(C_DIM / GBN, M_ROWS / GBM), 256>>>(
        yh, wtp, bproj, out, M_ROWS, C_DIM, C_DIM, 0);
}

// round 16
// speedup vs baseline: 1.8536x; 1.0321x over previous
#include <cuda_runtime.h>
#include <cuda_fp16.h>
#include <math.h>
#include <stdint.h>

// Shapes (fixed by the problem)
#define B_SZ   16
#define T_SEQ  1024
#define C_DIM  768
#define NH     12
#define DH     64
#define C3     2304       // 3*C
#define M_ROWS 16384      // B*T

// Scratch buffers (no cudaMalloc allowed) — fp16 storage end-to-end
__device__ __half g_xh[(size_t)M_ROWS * C_DIM];     // x in fp16
__device__ __half g_qkv_h[(size_t)M_ROWS * C3];     // qkv in fp16
__device__ __half g_y_h[(size_t)M_ROWS * C_DIM];    // attention out fp16
__device__ __half g_wt_qkv[(size_t)C3 * C_DIM];     // W_qkv^T fp16
__device__ __half g_wt_proj[(size_t)C_DIM * C_DIM]; // W_proj^T fp16

// ---------------------------------------------------------------------------
// Helpers
// ---------------------------------------------------------------------------
__device__ __forceinline__ uint32_t packh2(float a, float b) {
    __half2 h = __floats2half2_rn(a, b);
    return *(uint32_t*)&h;
}
__device__ __forceinline__ void mma_f16(float* c, const uint32_t* a, const uint32_t* b) {
    asm volatile(
        "mma.sync.aligned.m16n8k16.row.col.f32.f16.f16.f32 "
        "{%0,%1,%2,%3}, {%4,%5,%6,%7}, {%8,%9}, {%0,%1,%2,%3};"
        : "+f"(c[0]), "+f"(c[1]), "+f"(c[2]), "+f"(c[3])
        : "r"(a[0]), "r"(a[1]), "r"(a[2]), "r"(a[3]), "r"(b[0]), "r"(b[1]));
}
__device__ __forceinline__ void ldsm_x4(uint32_t* r, uint32_t addr) {
    asm volatile("ldmatrix.sync.aligned.m8n8.x4.shared.b16 {%0,%1,%2,%3}, [%4];"
                 : "=r"(r[0]), "=r"(r[1]), "=r"(r[2]), "=r"(r[3]) : "r"(addr));
}
__device__ __forceinline__ uint32_t a_ldsm_addr(uint32_t base_b, int lane, int am,
                                                int pitch_w, int kp0_w) {
    return base_b + (uint32_t)(((am + (lane & 15)) * pitch_w + kp0_w + (lane >> 4) * 4) * 4);
}
__device__ __forceinline__ uint32_t b_ldsm_addr(uint32_t base_b, int lane, int bn0,
                                                int pitch_w, int kp0_w) {
    int row = bn0 + (lane & 7) + ((lane >> 4) << 3);
    int col = kp0_w + ((lane >> 3) & 1) * 4;
    return base_b + (uint32_t)((row * pitch_w + col) * 4);
}

// ---------------------------------------------------------------------------
// Pre-pass kernels
// ---------------------------------------------------------------------------
__global__ void cvt_f2h(const float* __restrict__ in, __half* __restrict__ out, int n4)
{
    int i = blockIdx.x * blockDim.x + threadIdx.x;
    if (i < n4) {
        float4 v = *(const float4*)(in + 4 * (size_t)i);
        uint2 o;
        o.x = packh2(v.x, v.y);
        o.y = packh2(v.z, v.w);
        *(uint2*)(out + 4 * (size_t)i) = o;
    }
}

__global__ void tcvt(const float* __restrict__ in, __half* __restrict__ out, int R, int C)
{
    __shared__ float t[32][33];
    const int bx = blockIdx.x * 32;
    const int by = blockIdx.y * 32;
#pragma unroll
    for (int j = threadIdx.y; j < 32; j += 8)
        t[j][threadIdx.x] = in[(size_t)(by + j) * C + bx + threadIdx.x];
    __syncthreads();
#pragma unroll
    for (int j = threadIdx.y; j < 32; j += 8)
        out[(size_t)(bx + j) * R + by + threadIdx.x] = __float2half(t[threadIdx.x][j]);
}

// ---------------------------------------------------------------------------
// FP16 GEMM v9: compute-first double buffer — ONE __syncthreads per k-chunk.
// C = A[M,K] @ Bt[N,K]^T + bias. CTA 256x128, 8 warps (4x2), warp 64x64, BK=32.
// Stage s holds chunk c (s = c&1). Per iter: compute(s) -> STS c+1 into s^1 ->
// LDG c+2 -> sync. Dynamic smem: 2 stages x 30720 B = 61440 B.
// ---------------------------------------------------------------------------
#define GBM 256
#define GBN 128
#define GBK 32
#define AP16 20
#define BP16 20
#define GSTAGE_W (GBM * AP16 + GBN * BP16)       // 7680 words per stage
#define GEMM_SMEM (2 * GSTAGE_W * 4)             // 61440 B

__global__ __launch_bounds__(256, 1) void f16_gemm_bias(
    const __half* __restrict__ A, const __half* __restrict__ Bt,
    const float* __restrict__ bias, void* __restrict__ Cv,
    int M, int N, int K, int halfOut)
{
    extern __shared__ uint32_t gsm[];

    const int tid  = threadIdx.x;
    const int wid  = tid >> 5;
    const int lane = tid & 31;
    const int wm   = wid >> 1;
    const int wn   = wid & 1;
    const int g    = lane >> 2;
    const int tg   = lane & 3;

    const uint32_t s_base = (uint32_t)__cvta_generic_to_shared(gsm);

    // loaders: 8 threads per row, 4 halfs (uint2) each
    const int ar = tid >> 3;            // 0..31
    const int ac = (tid & 7) * 4;       // half col
    const int aw = ac >> 1;             // word col

    const __half* Ag = A  + (size_t)(blockIdx.y * GBM + ar) * K + ac;
    const __half* Bg = Bt + (size_t)(blockIdx.x * GBN + ar) * K + ac;

    float acc[4][8][4];
#pragma unroll
    for (int mt = 0; mt < 4; mt++)
#pragma unroll
        for (int nt = 0; nt < 8; nt++)
#pragma unroll
            for (int c = 0; c < 4; c++) acc[mt][nt][c] = 0.f;

    const int NCH = K / GBK;
    uint2 pa[8], pb[4];

    // ---- prologue: chunk0 -> stage0; chunk1 -> regs; one sync ----
#pragma unroll
    for (int i = 0; i < 8; i++) pa[i] = *(const uint2*)(Ag + (size_t)(32 * i) * K);
#pragma unroll
    for (int j = 0; j < 4; j++) pb[j] = *(const uint2*)(Bg + (size_t)(32 * j) * K);
    {
        uint32_t* As0 = gsm;
        uint32_t* Bs0 = gsm + GBM * AP16;
#pragma unroll
        for (int i = 0; i < 8; i++) *(uint2*)&As0[(ar + 32 * i) * AP16 + aw] = pa[i];
#pragma unroll
        for (int j = 0; j < 4; j++) *(uint2*)&Bs0[(ar + 32 * j) * BP16 + aw] = pb[j];
    }
    if (NCH > 1) {
#pragma unroll
        for (int i = 0; i < 8; i++)
            pa[i] = *(const uint2*)(Ag + (size_t)(32 * i) * K + GBK);
#pragma unroll
        for (int j = 0; j < 4; j++)
            pb[j] = *(const uint2*)(Bg + (size_t)(32 * j) * K + GBK);
    }
    __syncthreads();

    for (int c = 0; c < NCH; c++) {
        const int s = c & 1;
        const uint32_t a_rd = s_base + (uint32_t)(s * GSTAGE_W) * 4;
        const uint32_t b_rd = a_rd + (uint32_t)(GBM * AP16) * 4;

        // ---- compute chunk c from stage s ----
#pragma unroll
        for (int ks = 0; ks < 2; ks++) {
            const int kp0 = ks * 8;
            uint32_t af[4][4], bf[8][2];
#pragma unroll
            for (int mt = 0; mt < 4; mt++)
                ldsm_x4(af[mt], a_ldsm_addr(a_rd, lane, wm * 64 + mt * 16, AP16, kp0));
#pragma unroll
            for (int np = 0; np < 4; np++) {
                uint32_t r[4];
                ldsm_x4(r, b_ldsm_addr(b_rd, lane, wn * 64 + np * 16, BP16, kp0));
                bf[2 * np][0] = r[0]; bf[2 * np][1] = r[1];
                bf[2 * np + 1][0] = r[2]; bf[2 * np + 1][1] = r[3];
            }
#pragma unroll
            for (int mt = 0; mt < 4; mt++)
#pragma unroll
                for (int nt = 0; nt < 8; nt++)
                    mma_f16(acc[mt][nt], af[mt], bf[nt]);
        }

        // ---- STS chunk c+1 into stage s^1 (no conflict with reads of s) ----
        if (c + 1 < NCH) {
            uint32_t* Asw = gsm + (s ^ 1) * GSTAGE_W;
            uint32_t* Bsw = Asw + GBM * AP16;
#pragma unroll
            for (int i = 0; i < 8; i++) *(uint2*)&Asw[(ar + 32 * i) * AP16 + aw] = pa[i];
#pragma unroll
            for (int j = 0; j < 4; j++) *(uint2*)&Bsw[(ar + 32 * j) * BP16 + aw] = pb[j];
        }
        // ---- LDG chunk c+2 into regs ----
        if (c + 2 < NCH) {
            const int kofs = (c + 2) * GBK;
#pragma unroll
            for (int i = 0; i < 8; i++)
                pa[i] = *(const uint2*)(Ag + (size_t)(32 * i) * K + kofs);
#pragma unroll
            for (int j = 0; j < 4; j++)
                pb[j] = *(const uint2*)(Bg + (size_t)(32 * j) * K + kofs);
        }
        __syncthreads();
    }

    const int crow0 = blockIdx.y * GBM + wm * 64;
    const int ccol0 = blockIdx.x * GBN + wn * 64;
    if (halfOut) {
        __half* Ch = (__half*)Cv;
#pragma unroll
        for (int mt = 0; mt < 4; mt++) {
#pragma unroll
            for (int nt = 0; nt < 8; nt++) {
                const int row = crow0 + mt * 16 + g;
                const int col = ccol0 + nt * 8 + 2 * tg;
                const float b0 = bias[col], b1 = bias[col + 1];
                *(uint32_t*)(Ch + (size_t)row * N + col) =
                    packh2(acc[mt][nt][0] + b0, acc[mt][nt][1] + b1);
                *(uint32_t*)(Ch + (size_t)(row + 8) * N + col) =
                    packh2(acc[mt][nt][2] + b0, acc[mt][nt][3] + b1);
            }
        }
    } else {
        float* Cf = (float*)Cv;
#pragma unroll
        for (int mt = 0; mt < 4; mt++) {
#pragma unroll
            for (int nt = 0; nt < 8; nt++) {
                const int row = crow0 + mt * 16 + g;
                const int col = ccol0 + nt * 8 + 2 * tg;
                const float b0 = bias[col], b1 = bias[col + 1];
                *(float2*)(Cf + (size_t)row * N + col) =
                    make_float2(acc[mt][nt][0] + b0, acc[mt][nt][1] + b1);
                *(float2*)(Cf + (size_t)(row + 8) * N + col) =
                    make_float2(acc[mt][nt][2] + b0, acc[mt][nt][3] + b1);
            }
        }
    }
}

// ---------------------------------------------------------------------------
// Flash-attention v7: fp16 + ldmatrix + K/V double buffer, ONE sync per k-tile.
// q-tile 128, 4 warps; warp w owns rows 32w..32w+31 (mt=2).
// Smem words (pitch HP=36): Qh[128], Kh0[64], Kh1[64], Vt0[64], Vt1[64], Ph[128].
// ---------------------------------------------------------------------------
#define HP 36
#define ATTN_SMEM ((128 + 4 * 64 + 128) * HP * 4)   // 73728 B

__global__ __launch_bounds__(128, 2) void attn_mma_kernel(
    const __half* __restrict__ qkv, __half* __restrict__ y)
{
    extern __shared__ uint32_t smu[];
    uint32_t* Qh  = smu;                    // [128][HP]
    uint32_t* Kh0 = smu + 128 * HP;         // stages: Kh0, Kh1, Vt0, Vt1
    uint32_t* Ph  = smu + (128 + 4 * 64) * HP;

    const uint32_t base_b  = (uint32_t)__cvta_generic_to_shared(smu);
    const uint32_t qh_base = base_b;
    const uint32_t ph_base = base_b + (uint32_t)((128 + 4 * 64) * HP) * 4;

    const int q0 = blockIdx.x * 128;
    const int h  = blockIdx.y;
    const int b  = blockIdx.z;

    const int tid  = threadIdx.x;
    const int w    = tid >> 5;
    const int lane = tid & 31;
    const int g    = lane >> 2;
    const int tg   = lane & 3;

    const int lr = tid >> 1;              // 0..63
    const int hc = (tid & 1) * 32;        // half col base
    const int hw = hc >> 1;               // word base
    const int vr   = tid & 31;            // token pair
    const int vds  = (tid >> 5) * 16;     // d base

    const uint32_t sc = packh2(0.125f, 0.125f);
    const __half2 scale2 = *(const __half2*)&sc;

    // ---- load Q tile (scaled) ----
#pragma unroll
    for (int rh = 0; rh < 2; rh++) {
        const int rr = lr + 64 * rh;
        const __half* src = qkv + ((size_t)(b * T_SEQ + q0 + rr)) * C3 + h * DH + hc;
        uint32_t* dst = Qh + rr * HP + hw;
#pragma unroll
        for (int j = 0; j < 4; j++) {
            uint4 v = *(const uint4*)(src + 8 * j);
            __half2* hv = (__half2*)&v;
            hv[0] = __hmul2(hv[0], scale2);
            hv[1] = __hmul2(hv[1], scale2);
            hv[2] = __hmul2(hv[2], scale2);
            hv[3] = __hmul2(hv[3], scale2);
            *(uint4*)(dst + 4 * j) = v;
        }
    }

    const int ntiles = q0 / 64 + 2;

    // K/V prefetch registers
    uint4 kreg[4];
    uint32_t u0[8], u1[8];

    // LDG of tile t (k0 = 64t)
    auto ldg_kv = [&](int t) {
        const int k0 = 64 * t;
        const __half* kb = qkv + ((size_t)(b * T_SEQ + k0 + lr)) * C3 + C_DIM + h * DH + hc;
#pragma unroll
        for (int j = 0; j < 4; j++) kreg[j] = *(const uint4*)(kb + 8 * j);
        const __half* v0p = qkv + ((size_t)(b * T_SEQ + k0 + 2 * vr)) * C3 + 2 * C_DIM + h * DH + vds;
        const __half* v1p = v0p + C3;
        *(uint4*)(u0    ) = *(const uint4*)(v0p);
        *(uint4*)(u0 + 4) = *(const uint4*)(v0p + 8);
        *(uint4*)(u1    ) = *(const uint4*)(v1p);
        *(uint4*)(u1 + 4) = *(const uint4*)(v1p + 8);
    };
    // STS into stage s
    auto sts_kv = [&](int s) {
        uint32_t* kd = Kh0 + s * 64 * HP + lr * HP + hw;
#pragma unroll
        for (int j = 0; j < 4; j++) *(uint4*)(kd + 4 * j) = kreg[j];
        uint32_t* vt = Kh0 + (2 + s) * 64 * HP;
#pragma unroll
        for (int i = 0; i < 8; i++) {
            vt[(vds + 2 * i    ) * HP + vr] = __byte_perm(u0[i], u1[i], 0x5410);
            vt[(vds + 2 * i + 1) * HP + vr] = __byte_perm(u0[i], u1[i], 0x7632);
        }
    };

    // ---- prologue: tile0 -> stage0; tile1 -> regs; one sync ----
    ldg_kv(0);
    sts_kv(0);
    if (ntiles > 1) ldg_kv(1);

    float m[2][2], l[2][2], o[2][8][4];
#pragma unroll
    for (int mt = 0; mt < 2; mt++) {
        m[mt][0] = -1e30f; m[mt][1] = -1e30f;
        l[mt][0] = 0.f;    l[mt][1] = 0.f;
#pragma unroll
        for (int nt = 0; nt < 8; nt++)
#pragma unroll
            for (int c = 0; c < 4; c++) o[mt][nt][c] = 0.f;
    }

    const int rowg0 = 32 * w + g;
    __syncthreads();

    for (int c = 0; c < ntiles; c++) {
        const int s = c & 1;
        const int k0 = 64 * c;
        const uint32_t kh_rd = base_b + (uint32_t)((128 + s * 64) * HP) * 4;
        const uint32_t vt_rd = base_b + (uint32_t)((128 + (2 + s) * 64) * HP) * 4;

        // ---- S = Q @ K^T ----
        float sacc[2][8][4];
#pragma unroll
        for (int mt = 0; mt < 2; mt++)
#pragma unroll
            for (int nt = 0; nt < 8; nt++)
#pragma unroll
                for (int cc = 0; cc < 4; cc++) sacc[mt][nt][cc] = 0.f;

#pragma unroll
        for (int ks = 0; ks < 4; ks++) {
            const int kp0 = ks * 8;
            uint32_t af[2][4], bf[8][2];
#pragma unroll
            for (int mt = 0; mt < 2; mt++)
                ldsm_x4(af[mt], a_ldsm_addr(qh_base, lane, 32 * w + 16 * mt, HP, kp0));
#pragma unroll
            for (int np = 0; np < 4; np++) {
                uint32_t r[4];
                ldsm_x4(r, b_ldsm_addr(kh_rd, lane, np * 16, HP, kp0));
                bf[2 * np][0] = r[0]; bf[2 * np][1] = r[1];
                bf[2 * np + 1][0] = r[2]; bf[2 * np + 1][1] = r[3];
            }
#pragma unroll
            for (int nt = 0; nt < 8; nt++) {
                mma_f16(sacc[0][nt], af[0], bf[nt]);
                mma_f16(sacc[1][nt], af[1], bf[nt]);
            }
        }

        // ---- causal mask ----
        if (k0 >= q0) {
            const int dk = k0 - q0;
#pragma unroll
            for (int mt = 0; mt < 2; mt++) {
                const int r0 = rowg0 + 16 * mt;
#pragma unroll
                for (int nt = 0; nt < 8; nt++) {
                    const int c0 = nt * 8 + 2 * tg + dk;
                    if (c0     > r0    ) sacc[mt][nt][0] = -1e30f;
                    if (c0 + 1 > r0    ) sacc[mt][nt][1] = -1e30f;
                    if (c0     > r0 + 8) sacc[mt][nt][2] = -1e30f;
                    if (c0 + 1 > r0 + 8) sacc[mt][nt][3] = -1e30f;
                }
            }
        }

        // ---- online softmax ----
#pragma unroll
        for (int mt = 0; mt < 2; mt++) {
            float mx0 = -1e30f, mx1 = -1e30f;
#pragma unroll
            for (int nt = 0; nt < 8; nt++) {
                mx0 = fmaxf(mx0, fmaxf(sacc[mt][nt][0], sacc[mt][nt][1]));
                mx1 = fmaxf(mx1, fmaxf(sacc[mt][nt][2], sacc[mt][nt][3]));
            }
            mx0 = fmaxf(mx0, __shfl_xor_sync(0xffffffffu, mx0, 1));
            mx0 = fmaxf(mx0, __shfl_xor_sync(0xffffffffu, mx0, 2));
            mx1 = fmaxf(mx1, __shfl_xor_sync(0xffffffffu, mx1, 1));
            mx1 = fmaxf(mx1, __shfl_xor_sync(0xffffffffu, mx1, 2));

            const float mn0 = fmaxf(m[mt][0], mx0);
            const float mn1 = fmaxf(m[mt][1], mx1);
            const float f0  = __expf(m[mt][0] - mn0);
            const float f1  = __expf(m[mt][1] - mn1);

            const int r0 = rowg0 + 16 * mt;
            float sum0 = 0.f, sum1 = 0.f;
#pragma unroll
            for (int nt = 0; nt < 8; nt++) {
                float p0 = __expf(sacc[mt][nt][0] - mn0);
                float p1 = __expf(sacc[mt][nt][1] - mn0);
                float p2 = __expf(sacc[mt][nt][2] - mn1);
                float p3 = __expf(sacc[mt][nt][3] - mn1);
                sum0 += p0 + p1;
                sum1 += p2 + p3;
                Ph[(r0    ) * HP + nt * 4 + tg] = packh2(p0, p1);
                Ph[(r0 + 8) * HP + nt * 4 + tg] = packh2(p2, p3);
            }
            sum0 += __shfl_xor_sync(0xffffffffu, sum0, 1);
            sum0 += __shfl_xor_sync(0xffffffffu, sum0, 2);
            sum1 += __shfl_xor_sync(0xffffffffu, sum1, 1);
            sum1 += __shfl_xor_sync(0xffffffffu, sum1, 2);

            l[mt][0] = l[mt][0] * f0 + sum0;  m[mt][0] = mn0;
            l[mt][1] = l[mt][1] * f1 + sum1;  m[mt][1] = mn1;
#pragma unroll
            for (int nt = 0; nt < 8; nt++) {
                o[mt][nt][0] *= f0; o[mt][nt][1] *= f0;
                o[mt][nt][2] *= f1; o[mt][nt][3] *= f1;
            }
        }
        __syncwarp();

        // ---- O += P @ V ----
#pragma unroll
        for (int ks = 0; ks < 4; ks++) {
            const int kp0 = ks * 8;
            uint32_t af[2][4], bf[8][2];
#pragma unroll
            for (int mt = 0; mt < 2; mt++)
                ldsm_x4(af[mt], a_ldsm_addr(ph_base, lane, 32 * w + 16 * mt, HP, kp0));
#pragma unroll
            for (int np = 0; np < 4; np++) {
                uint32_t r[4];
                ldsm_x4(r, b_ldsm_addr(vt_rd, lane, np * 16, HP, kp0));
                bf[2 * np][0] = r[0]; bf[2 * np][1] = r[1];
                bf[2 * np + 1][0] = r[2]; bf[2 * np + 1][1] = r[3];
            }
#pragma unroll
            for (int nt = 0; nt < 8; nt++) {
                mma_f16(o[0][nt], af[0], bf[nt]);
                mma_f16(o[1][nt], af[1], bf[nt]);
            }
        }

        // ---- STS tile c+1 into stage s^1; LDG tile c+2; one sync ----
        if (c + 1 < ntiles) sts_kv(s ^ 1);
        if (c + 2 < ntiles) ldg_kv(c + 2);
        __syncthreads();
    }

    // ---- normalize, stage as fp16 pairs (reuse Qh region), coalesced write ----
    uint32_t* Of = smu;   // [128][HP] half-pairs
#pragma unroll
    for (int mt = 0; mt < 2; mt++) {
        const int r0 = rowg0 + 16 * mt;
        const float inv0 = 1.f / l[mt][0];
        const float inv1 = 1.f / l[mt][1];
#pragma unroll
        for (int nt = 0; nt < 8; nt++) {
            Of[(r0    ) * HP + nt * 4 + tg] = packh2(o[mt][nt][0] * inv0, o[mt][nt][1] * inv0);
            Of[(r0 + 8) * HP + nt * 4 + tg] = packh2(o[mt][nt][2] * inv1, o[mt][nt][3] * inv1);
        }
    }
    __syncthreads();
#pragma unroll
    for (int rh = 0; rh < 2; rh++) {
        const int rr = lr + 64 * rh;
        const uint32_t* src = Of + rr * HP + hw;
        __half* dst = y + ((size_t)(b * T_SEQ + q0 + rr)) * C_DIM + h * DH + hc;
#pragma unroll
        for (int j = 0; j < 4; j++)
            *(uint4*)(dst + 8 * j) = *(const uint4*)(src + 4 * j);
    }
}

// ---------------------------------------------------------------------------
extern "C" void kernel_launch(void* const* d_in, const int* in_sizes, int n_in,
                              void* d_out, int out_size)
{
    const float* x     = (const float*)d_in[0];
    const float* Wqkv  = (const float*)d_in[1];
    const float* bqkv  = (const float*)d_in[2];
    const float* Wproj = (const float*)d_in[3];
    const float* bproj = (const float*)d_in[4];
    float* out = (float*)d_out;

    __half *xh, *qkvh, *yh, *wtq, *wtp;
    cudaGetSymbolAddress((void**)&xh, g_xh);
    cudaGetSymbolAddress((void**)&qkvh, g_qkv_h);
    cudaGetSymbolAddress((void**)&yh, g_y_h);
    cudaGetSymbolAddress((void**)&wtq, g_wt_qkv);
    cudaGetSymbolAddress((void**)&wtp, g_wt_proj);

    cudaFuncSetAttribute(f16_gemm_bias,
                         cudaFuncAttributeMaxDynamicSharedMemorySize, GEMM_SMEM);
    cudaFuncSetAttribute(attn_mma_kernel,
                         cudaFuncAttributeMaxDynamicSharedMemorySize, ATTN_SMEM);

    // 0) pre-pass: x -> fp16; weights -> fp16 transposed [N][K]
    {
        const int n4 = (M_ROWS * C_DIM) / 4;
        cvt_f2h<<<(n4 + 255) / 256, 256>>>(x, xh, n4);
        tcvt<<<dim3(C3 / 32, C_DIM / 32), dim3(32, 8)>>>(Wqkv, wtq, C_DIM, C3);
        tcvt<<<dim3(C_DIM / 32, C_DIM / 32), dim3(32, 8)>>>(Wproj, wtp, C_DIM, C_DIM);
    }

    // 1) QKV projection (fp16 in, fp16 out)
    f16_gemm_bias<<<dim3(C3 / GBN, M_ROWS / GBM), 256, GEMM_SMEM>>>(
        xh, wtq, bqkv, qkvh, M_ROWS, C3, C_DIM, 1);

    // 2) causal attention (fp16 in, fp16 out)
    attn_mma_kernel<<<dim3(T_SEQ / 128, NH, B_SZ), 128, ATTN_SMEM>>>(qkvh, yh);

    // 3) output projection (fp16 in, fp32 out)
    f16_gemm_bias<<<dim3(C_DIM / GBN, M_ROWS / GBM), 256, GEMM_SMEM>>>(
        yh, wtp, bproj, out, M_ROWS, C_DIM, C_DIM, 0);
}

// round 17
// speedup vs baseline: 1.9187x; 1.0351x over previous
#include <cuda_runtime.h>
#include <cuda_fp16.h>
#include <math.h>
#include <stdint.h>

// Shapes (fixed by the problem)
#define B_SZ   16
#define T_SEQ  1024
#define C_DIM  768
#define NH     12
#define DH     64
#define C3     2304       // 3*C
#define M_ROWS 16384      // B*T

// Scratch buffers (no cudaMalloc allowed) — fp16 storage end-to-end
__device__ __half g_xh[(size_t)M_ROWS * C_DIM];     // x in fp16
__device__ __half g_qkv_h[(size_t)M_ROWS * C3];     // qkv in fp16
__device__ __half g_y_h[(size_t)M_ROWS * C_DIM];    // attention out fp16
__device__ __half g_wt_qkv[(size_t)C3 * C_DIM];     // W_qkv^T fp16
__device__ __half g_wt_proj[(size_t)C_DIM * C_DIM]; // W_proj^T fp16

// ---------------------------------------------------------------------------
// Helpers
// ---------------------------------------------------------------------------
__device__ __forceinline__ uint32_t packh2(float a, float b) {
    __half2 h = __floats2half2_rn(a, b);
    return *(uint32_t*)&h;
}
__device__ __forceinline__ void mma_f16(float* c, const uint32_t* a, const uint32_t* b) {
    asm volatile(
        "mma.sync.aligned.m16n8k16.row.col.f32.f16.f16.f32 "
        "{%0,%1,%2,%3}, {%4,%5,%6,%7}, {%8,%9}, {%0,%1,%2,%3};"
        : "+f"(c[0]), "+f"(c[1]), "+f"(c[2]), "+f"(c[3])
        : "r"(a[0]), "r"(a[1]), "r"(a[2]), "r"(a[3]), "r"(b[0]), "r"(b[1]));
}
__device__ __forceinline__ void ldsm_x4(uint32_t* r, uint32_t addr) {
    asm volatile("ldmatrix.sync.aligned.m8n8.x4.shared.b16 {%0,%1,%2,%3}, [%4];"
                 : "=r"(r[0]), "=r"(r[1]), "=r"(r[2]), "=r"(r[3]) : "r"(addr));
}
__device__ __forceinline__ uint32_t a_ldsm_addr(uint32_t base_b, int lane, int am,
                                                int pitch_w, int kp0_w) {
    return base_b + (uint32_t)(((am + (lane & 15)) * pitch_w + kp0_w + (lane >> 4) * 4) * 4);
}
__device__ __forceinline__ uint32_t b_ldsm_addr(uint32_t base_b, int lane, int bn0,
                                                int pitch_w, int kp0_w) {
    int row = bn0 + (lane & 7) + ((lane >> 4) << 3);
    int col = kp0_w + ((lane >> 3) & 1) * 4;
    return base_b + (uint32_t)((row * pitch_w + col) * 4);
}
__device__ __forceinline__ void cp_async8(uint32_t dst, const void* src) {
    asm volatile("cp.async.ca.shared.global [%0], [%1], 8;" :: "r"(dst), "l"(src));
}
#define CP_COMMIT() asm volatile("cp.async.commit_group;" ::: "memory")
#define CP_WAIT(n)  asm volatile("cp.async.wait_group %0;" :: "n"(n) : "memory")

// ---------------------------------------------------------------------------
// Pre-pass kernels
// ---------------------------------------------------------------------------
__global__ void cvt_f2h(const float* __restrict__ in, __half* __restrict__ out, int n4)
{
    int i = blockIdx.x * blockDim.x + threadIdx.x;
    if (i < n4) {
        float4 v = *(const float4*)(in + 4 * (size_t)i);
        uint2 o;
        o.x = packh2(v.x, v.y);
        o.y = packh2(v.z, v.w);
        *(uint2*)(out + 4 * (size_t)i) = o;
    }
}

__global__ void tcvt(const float* __restrict__ in, __half* __restrict__ out, int R, int C)
{
    __shared__ float t[32][33];
    const int bx = blockIdx.x * 32;
    const int by = blockIdx.y * 32;
#pragma unroll
    for (int j = threadIdx.y; j < 32; j += 8)
        t[j][threadIdx.x] = in[(size_t)(by + j) * C + bx + threadIdx.x];
    __syncthreads();
#pragma unroll
    for (int j = threadIdx.y; j < 32; j += 8)
        out[(size_t)(bx + j) * R + by + threadIdx.x] = __float2half(t[threadIdx.x][j]);
}

// ---------------------------------------------------------------------------
// FP16 GEMM v10: cp.async 3-stage pipeline, ONE __syncthreads per k-chunk,
// single L1TEX pass for gmem->smem. CTA 256x128, 8 warps (4x2), warp 64x64,
// BK=32. Chunk c lives in stage c%3. Per iter: compute(c%3) -> cp.async
// chunk c+2 -> stage (c+2)%3 -> wait(c+1 done) -> sync.
// ---------------------------------------------------------------------------
#define GBM 256
#define GBN 128
#define GBK 32
#define AP16 20
#define BP16 20
#define GSTAGE_W (GBM * AP16 + GBN * BP16)       // 7680 words per stage
#define GEMM_SMEM (3 * GSTAGE_W * 4)             // 92160 B

__global__ __launch_bounds__(256, 1) void f16_gemm_bias(
    const __half* __restrict__ A, const __half* __restrict__ Bt,
    const float* __restrict__ bias, void* __restrict__ Cv,
    int M, int N, int K, int halfOut)
{
    extern __shared__ uint32_t gsm[];

    const int tid  = threadIdx.x;
    const int wid  = tid >> 5;
    const int lane = tid & 31;
    const int wm   = wid >> 1;
    const int wn   = wid & 1;
    const int g    = lane >> 2;
    const int tg   = lane & 3;

    const uint32_t s_base = (uint32_t)__cvta_generic_to_shared(gsm);

    // loaders: 8 threads per row, 4 halfs (8 B) each
    const int ar = tid >> 3;            // 0..31
    const int ac = (tid & 7) * 4;       // half col
    const int aw = ac >> 1;             // word col

    const __half* Ag = A  + (size_t)(blockIdx.y * GBM + ar) * K + ac;
    const __half* Bg = Bt + (size_t)(blockIdx.x * GBN + ar) * K + ac;

    const int NCH = K / GBK;

    // issue cp.async for chunk c into stage st
    auto issue_chunk = [&](int c, int st) {
        const int kofs = c * GBK;
        const uint32_t abase = s_base + (uint32_t)(st * GSTAGE_W) * 4;
        const uint32_t bbase = abase + (uint32_t)(GBM * AP16) * 4;
#pragma unroll
        for (int i = 0; i < 8; i++)
            cp_async8(abase + (uint32_t)(((ar + 32 * i) * AP16 + aw) * 4),
                      Ag + (size_t)(32 * i) * K + kofs);
#pragma unroll
        for (int j = 0; j < 4; j++)
            cp_async8(bbase + (uint32_t)(((ar + 32 * j) * BP16 + aw) * 4),
                      Bg + (size_t)(32 * j) * K + kofs);
        CP_COMMIT();
    };

    float acc[4][8][4];
#pragma unroll
    for (int mt = 0; mt < 4; mt++)
#pragma unroll
        for (int nt = 0; nt < 8; nt++)
#pragma unroll
            for (int c = 0; c < 4; c++) acc[mt][nt][c] = 0.f;

    // ---- prologue: chunks 0 and 1 in flight; wait chunk0; sync ----
    issue_chunk(0, 0);
    if (NCH > 1) issue_chunk(1, 1);
    CP_WAIT(1);
    __syncthreads();

    for (int c = 0; c < NCH; c++) {
        const int s = c % 3;
        const uint32_t a_rd = s_base + (uint32_t)(s * GSTAGE_W) * 4;
        const uint32_t b_rd = a_rd + (uint32_t)(GBM * AP16) * 4;

        // ---- compute chunk c from stage s ----
#pragma unroll
        for (int ks = 0; ks < 2; ks++) {
            const int kp0 = ks * 8;
            uint32_t af[4][4], bf[8][2];
#pragma unroll
            for (int mt = 0; mt < 4; mt++)
                ldsm_x4(af[mt], a_ldsm_addr(a_rd, lane, wm * 64 + mt * 16, AP16, kp0));
#pragma unroll
            for (int np = 0; np < 4; np++) {
                uint32_t r[4];
                ldsm_x4(r, b_ldsm_addr(b_rd, lane, wn * 64 + np * 16, BP16, kp0));
                bf[2 * np][0] = r[0]; bf[2 * np][1] = r[1];
                bf[2 * np + 1][0] = r[2]; bf[2 * np + 1][1] = r[3];
            }
#pragma unroll
            for (int mt = 0; mt < 4; mt++)
#pragma unroll
                for (int nt = 0; nt < 8; nt++)
                    mma_f16(acc[mt][nt], af[mt], bf[nt]);
        }

        // ---- keep the pipe full: chunk c+2 -> stage (c+2)%3 ----
        if (c + 2 < NCH) {
            issue_chunk(c + 2, (c + 2) % 3);
            CP_WAIT(1);          // chunk c+1 complete
        } else {
            CP_WAIT(0);          // drain (covers tail, incl. chunk c+1)
        }
        __syncthreads();
    }

    const int crow0 = blockIdx.y * GBM + wm * 64;
    const int ccol0 = blockIdx.x * GBN + wn * 64;
    if (halfOut) {
        __half* Ch = (__half*)Cv;
#pragma unroll
        for (int mt = 0; mt < 4; mt++) {
#pragma unroll
            for (int nt = 0; nt < 8; nt++) {
                const int row = crow0 + mt * 16 + g;
                const int col = ccol0 + nt * 8 + 2 * tg;
                const float b0 = bias[col], b1 = bias[col + 1];
                *(uint32_t*)(Ch + (size_t)row * N + col) =
                    packh2(acc[mt][nt][0] + b0, acc[mt][nt][1] + b1);
                *(uint32_t*)(Ch + (size_t)(row + 8) * N + col) =
                    packh2(acc[mt][nt][2] + b0, acc[mt][nt][3] + b1);
            }
        }
    } else {
        float* Cf = (float*)Cv;
#pragma unroll
        for (int mt = 0; mt < 4; mt++) {
#pragma unroll
            for (int nt = 0; nt < 8; nt++) {
                const int row = crow0 + mt * 16 + g;
                const int col = ccol0 + nt * 8 + 2 * tg;
                const float b0 = bias[col], b1 = bias[col + 1];
                *(float2*)(Cf + (size_t)row * N + col) =
                    make_float2(acc[mt][nt][0] + b0, acc[mt][nt][1] + b1);
                *(float2*)(Cf + (size_t)(row + 8) * N + col) =
                    make_float2(acc[mt][nt][2] + b0, acc[mt][nt][3] + b1);
            }
        }
    }
}

// ---------------------------------------------------------------------------
// Flash-attention v8: fp16 + ldmatrix + K/V double buffer (R16 structure)
// + per-warp causal tile skip: warp w needs tile k0 only if
// k0 <= q0 + 32w + 31 (last tile fully masked for warps 0,1 — skip it).
// Smem words (pitch HP=36): Qh[128], Kh0, Kh1, Vt0, Vt1 (64 each), Ph[128].
// ---------------------------------------------------------------------------
#define HP 36
#define ATTN_SMEM ((128 + 4 * 64 + 128) * HP * 4)   // 73728 B

__global__ __launch_bounds__(128, 2) void attn_mma_kernel(
    const __half* __restrict__ qkv, __half* __restrict__ y)
{
    extern __shared__ uint32_t smu[];
    uint32_t* Qh  = smu;                    // [128][HP]
    uint32_t* Kh0 = smu + 128 * HP;         // stages: Kh0, Kh1, Vt0, Vt1
    uint32_t* Ph  = smu + (128 + 4 * 64) * HP;

    const uint32_t base_b  = (uint32_t)__cvta_generic_to_shared(smu);
    const uint32_t qh_base = base_b;
    const uint32_t ph_base = base_b + (uint32_t)((128 + 4 * 64) * HP) * 4;

    const int q0 = blockIdx.x * 128;
    const int h  = blockIdx.y;
    const int b  = blockIdx.z;

    const int tid  = threadIdx.x;
    const int w    = tid >> 5;
    const int lane = tid & 31;
    const int g    = lane >> 2;
    const int tg   = lane & 3;

    const int lr = tid >> 1;              // 0..63
    const int hc = (tid & 1) * 32;        // half col base
    const int hw = hc >> 1;               // word base
    const int vr   = tid & 31;            // token pair
    const int vds  = (tid >> 5) * 16;     // d base

    const uint32_t sc = packh2(0.125f, 0.125f);
    const __half2 scale2 = *(const __half2*)&sc;

    // ---- load Q tile (scaled) ----
#pragma unroll
    for (int rh = 0; rh < 2; rh++) {
        const int rr = lr + 64 * rh;
        const __half* src = qkv + ((size_t)(b * T_SEQ + q0 + rr)) * C3 + h * DH + hc;
        uint32_t* dst = Qh + rr * HP + hw;
#pragma unroll
        for (int j = 0; j < 4; j++) {
            uint4 v = *(const uint4*)(src + 8 * j);
            __half2* hv = (__half2*)&v;
            hv[0] = __hmul2(hv[0], scale2);
            hv[1] = __hmul2(hv[1], scale2);
            hv[2] = __hmul2(hv[2], scale2);
            hv[3] = __hmul2(hv[3], scale2);
            *(uint4*)(dst + 4 * j) = v;
        }
    }

    const int ntiles = q0 / 64 + 2;

    uint4 kreg[4];
    uint32_t u0[8], u1[8];

    auto ldg_kv = [&](int t) {
        const int k0 = 64 * t;
        const __half* kb = qkv + ((size_t)(b * T_SEQ + k0 + lr)) * C3 + C_DIM + h * DH + hc;
#pragma unroll
        for (int j = 0; j < 4; j++) kreg[j] = *(const uint4*)(kb + 8 * j);
        const __half* v0p = qkv + ((size_t)(b * T_SEQ + k0 + 2 * vr)) * C3 + 2 * C_DIM + h * DH + vds;
        const __half* v1p = v0p + C3;
        *(uint4*)(u0    ) = *(const uint4*)(v0p);
        *(uint4*)(u0 + 4) = *(const uint4*)(v0p + 8);
        *(uint4*)(u1    ) = *(const uint4*)(v1p);
        *(uint4*)(u1 + 4) = *(const uint4*)(v1p + 8);
    };
    auto sts_kv = [&](int s) {
        uint32_t* kd = Kh0 + s * 64 * HP + lr * HP + hw;
#pragma unroll
        for (int j = 0; j < 4; j++) *(uint4*)(kd + 4 * j) = kreg[j];
        uint32_t* vt = Kh0 + (2 + s) * 64 * HP;
#pragma unroll
        for (int i = 0; i < 8; i++) {
            vt[(vds + 2 * i    ) * HP + vr] = __byte_perm(u0[i], u1[i], 0x5410);
            vt[(vds + 2 * i + 1) * HP + vr] = __byte_perm(u0[i], u1[i], 0x7632);
        }
    };

    ldg_kv(0);
    sts_kv(0);
    if (ntiles > 1) ldg_kv(1);

    float m[2][2], l[2][2], o[2][8][4];
#pragma unroll
    for (int mt = 0; mt < 2; mt++) {
        m[mt][0] = -1e30f; m[mt][1] = -1e30f;
        l[mt][0] = 0.f;    l[mt][1] = 0.f;
#pragma unroll
        for (int nt = 0; nt < 8; nt++)
#pragma unroll
            for (int c = 0; c < 4; c++) o[mt][nt][c] = 0.f;
    }

    const int rowg0 = 32 * w + g;
    __syncthreads();

    for (int c = 0; c < ntiles; c++) {
        const int s = c & 1;
        const int k0 = 64 * c;
        const uint32_t kh_rd = base_b + (uint32_t)((128 + s * 64) * HP) * 4;
        const uint32_t vt_rd = base_b + (uint32_t)((128 + (2 + s) * 64) * HP) * 4;

        // warp-uniform causal skip: does this warp's strip need tile k0?
        const bool active = (k0 <= q0 + 32 * w + 31);
        if (active) {
            // ---- S = Q @ K^T ----
            float sacc[2][8][4];
#pragma unroll
            for (int mt = 0; mt < 2; mt++)
#pragma unroll
                for (int nt = 0; nt < 8; nt++)
#pragma unroll
                    for (int cc = 0; cc < 4; cc++) sacc[mt][nt][cc] = 0.f;

#pragma unroll
            for (int ks = 0; ks < 4; ks++) {
                const int kp0 = ks * 8;
                uint32_t af[2][4], bf[8][2];
#pragma unroll
                for (int mt = 0; mt < 2; mt++)
                    ldsm_x4(af[mt], a_ldsm_addr(qh_base, lane, 32 * w + 16 * mt, HP, kp0));
#pragma unroll
                for (int np = 0; np < 4; np++) {
                    uint32_t r[4];
                    ldsm_x4(r, b_ldsm_addr(kh_rd, lane, np * 16, HP, kp0));
                    bf[2 * np][0] = r[0]; bf[2 * np][1] = r[1];
                    bf[2 * np + 1][0] = r[2]; bf[2 * np + 1][1] = r[3];
                }
#pragma unroll
                for (int nt = 0; nt < 8; nt++) {
                    mma_f16(sacc[0][nt], af[0], bf[nt]);
                    mma_f16(sacc[1][nt], af[1], bf[nt]);
                }
            }

            // ---- causal mask ----
            if (k0 >= q0) {
                const int dk = k0 - q0;
#pragma unroll
                for (int mt = 0; mt < 2; mt++) {
                    const int r0 = rowg0 + 16 * mt;
#pragma unroll
                    for (int nt = 0; nt < 8; nt++) {
                        const int c0 = nt * 8 + 2 * tg + dk;
                        if (c0     > r0    ) sacc[mt][nt][0] = -1e30f;
                        if (c0 + 1 > r0    ) sacc[mt][nt][1] = -1e30f;
                        if (c0     > r0 + 8) sacc[mt][nt][2] = -1e30f;
                        if (c0 + 1 > r0 + 8) sacc[mt][nt][3] = -1e30f;
                    }
                }
            }

            // ---- online softmax ----
#pragma unroll
            for (int mt = 0; mt < 2; mt++) {
                float mx0 = -1e30f, mx1 = -1e30f;
#pragma unroll
                for (int nt = 0; nt < 8; nt++) {
                    mx0 = fmaxf(mx0, fmaxf(sacc[mt][nt][0], sacc[mt][nt][1]));
                    mx1 = fmaxf(mx1, fmaxf(sacc[mt][nt][2], sacc[mt][nt][3]));
                }
                mx0 = fmaxf(mx0, __shfl_xor_sync(0xffffffffu, mx0, 1));
                mx0 = fmaxf(mx0, __shfl_xor_sync(0xffffffffu, mx0, 2));
                mx1 = fmaxf(mx1, __shfl_xor_sync(0xffffffffu, mx1, 1));
                mx1 = fmaxf(mx1, __shfl_xor_sync(0xffffffffu, mx1, 2));

                const float mn0 = fmaxf(m[mt][0], mx0);
                const float mn1 = fmaxf(m[mt][1], mx1);
                const float f0  = __expf(m[mt][0] - mn0);
                const float f1  = __expf(m[mt][1] - mn1);

                const int r0 = rowg0 + 16 * mt;
                float sum0 = 0.f, sum1 = 0.f;
#pragma unroll
                for (int nt = 0; nt < 8; nt++) {
                    float p0 = __expf(sacc[mt][nt][0] - mn0);
                    float p1 = __expf(sacc[mt][nt][1] - mn0);
                    float p2 = __expf(sacc[mt][nt][2] - mn1);
                    float p3 = __expf(sacc[mt][nt][3] - mn1);
                    sum0 += p0 + p1;
                    sum1 += p2 + p3;
                    Ph[(r0    ) * HP + nt * 4 + tg] = packh2(p0, p1);
                    Ph[(r0 + 8) * HP + nt * 4 + tg] = packh2(p2, p3);
                }
                sum0 += __shfl_xor_sync(0xffffffffu, sum0, 1);
                sum0 += __shfl_xor_sync(0xffffffffu, sum0, 2);
                sum1 += __shfl_xor_sync(0xffffffffu, sum1, 1);
                sum1 += __shfl_xor_sync(0xffffffffu, sum1, 2);

                l[mt][0] = l[mt][0] * f0 + sum0;  m[mt][0] = mn0;
                l[mt][1] = l[mt][1] * f1 + sum1;  m[mt][1] = mn1;
#pragma unroll
                for (int nt = 0; nt < 8; nt++) {
                    o[mt][nt][0] *= f0; o[mt][nt][1] *= f0;
                    o[mt][nt][2] *= f1; o[mt][nt][3] *= f1;
                }
            }
            __syncwarp();

            // ---- O += P @ V ----
#pragma unroll
            for (int ks = 0; ks < 4; ks++) {
                const int kp0 = ks * 8;
                uint32_t af[2][4], bf[8][2];
#pragma unroll
                for (int mt = 0; mt < 2; mt++)
                    ldsm_x4(af[mt], a_ldsm_addr(ph_base, lane, 32 * w + 16 * mt, HP, kp0));
#pragma unroll
                for (int np = 0; np < 4; np++) {
                    uint32_t r[4];
                    ldsm_x4(r, b_ldsm_addr(vt_rd, lane, np * 16, HP, kp0));
                    bf[2 * np][0] = r[0]; bf[2 * np][1] = r[1];
                    bf[2 * np + 1][0] = r[2]; bf[2 * np + 1][1] = r[3];
                }
#pragma unroll
                for (int nt = 0; nt < 8; nt++) {
                    mma_f16(o[0][nt], af[0], bf[nt]);
                    mma_f16(o[1][nt], af[1], bf[nt]);
                }
            }
        }

        // ---- STS tile c+1 into stage s^1; LDG tile c+2; one sync ----
        if (c + 1 < ntiles) sts_kv(s ^ 1);
        if (c + 2 < ntiles) ldg_kv(c + 2);
        __syncthreads();
    }

    // ---- normalize, stage as fp16 pairs (reuse Qh region), coalesced write ----
    uint32_t* Of = smu;   // [128][HP] half-pairs
#pragma unroll
    for (int mt = 0; mt < 2; mt++) {
        const int r0 = rowg0 + 16 * mt;
        const float inv0 = 1.f / l[mt][0];
        const float inv1 = 1.f / l[mt][1];
#pragma unroll
        for (int nt = 0; nt < 8; nt++) {
            Of[(r0    ) * HP + nt * 4 + tg] = packh2(o[mt][nt][0] * inv0, o[mt][nt][1] * inv0);
            Of[(r0 + 8) * HP + nt * 4 + tg] = packh2(o[mt][nt][2] * inv1, o[mt][nt][3] * inv1);
        }
    }
    __syncthreads();
#pragma unroll
    for (int rh = 0; rh < 2; rh++) {
        const int rr = lr + 64 * rh;
        const uint32_t* src = Of + rr * HP + hw;
        __half* dst = y + ((size_t)(b * T_SEQ + q0 + rr)) * C_DIM + h * DH + hc;
#pragma unroll
        for (int j = 0; j < 4; j++)
            *(uint4*)(dst + 8 * j) = *(const uint4*)(src + 4 * j);
    }
}

// ---------------------------------------------------------------------------
extern "C" void kernel_launch(void* const* d_in, const int* in_sizes, int n_in,
                              void* d_out, int out_size)
{
    const float* x     = (const float*)d_in[0];
    const float* Wqkv  = (const float*)d_in[1];
    const float* bqkv  = (const float*)d_in[2];
    const float* Wproj = (const float*)d_in[3];
    const float* bproj = (const float*)d_in[4];
    float* out = (float*)d_out;

    __half *xh, *qkvh, *yh, *wtq, *wtp;
    cudaGetSymbolAddress((void**)&xh, g_xh);
    cudaGetSymbolAddress((void**)&qkvh, g_qkv_h);
    cudaGetSymbolAddress((void**)&yh, g_y_h);
    cudaGetSymbolAddress((void**)&wtq, g_wt_qkv);
    cudaGetSymbolAddress((void**)&wtp, g_wt_proj);

    cudaFuncSetAttribute(f16_gemm_bias,
                         cudaFuncAttributeMaxDynamicSharedMemorySize, GEMM_SMEM);
    cudaFuncSetAttribute(attn_mma_kernel,
                         cudaFuncAttributeMaxDynamicSharedMemorySize, ATTN_SMEM);

    // 0) pre-pass: x -> fp16; weights -> fp16 transposed [N][K]
    {
        const int n4 = (M_ROWS * C_DIM) / 4;
        cvt_f2h<<<(n4 + 255) / 256, 256>>>(x, xh, n4);
        tcvt<<<dim3(C3 / 32, C_DIM / 32), dim3(32, 8)>>>(Wqkv, wtq, C_DIM, C3);
        tcvt<<<dim3(C_DIM / 32, C_DIM / 32), dim3(32, 8)>>>(Wproj, wtp, C_DIM, C_DIM);
    }

    // 1) QKV projection (fp16 in, fp16 out)
    f16_gemm_bias<<<dim3(C3 / GBN, M_ROWS / GBM), 256, GEMM_SMEM>>>(
        xh, wtq, bqkv, qkvh, M_ROWS, C3, C_DIM, 1);

    // 2) causal attention (fp16 in, fp16 out)
    attn_mma_kernel<<<dim3(T_SEQ / 128, NH, B_SZ), 128, ATTN_SMEM>>>(qkvh, yh);

    // 3) output projection (fp16 in, fp32 out)
    f16_gemm_bias<<<dim3(C_DIM / GBN, M_ROWS / GBM), 256, GEMM_SMEM>>>(
        yh, wtp, bproj, out, M_ROWS, C_DIM, C_DIM, 0);
}